// round 3
// baseline (speedup 1.0000x reference)
#include <cuda_runtime.h>
#include <mma.h>

using namespace nvcuda;

#define CC 2048
#define HWN 4096

// ---------------- device scratch ----------------
__device__ float g_sum[128];
__device__ float g_sumsq[128];
__device__ float g_hs4[4*1024*192];   // 4 K-splits of sampled raw dot products
__device__ float g_loss[16];

__global__ void k_init0() {
    int t = threadIdx.x;
    if (t < 128) { g_sum[t] = 0.f; g_sumsq[t] = 0.f; }
}

// ---------------- cp.async helpers ----------------
__device__ __forceinline__ void cpasync16(void* s, const void* g) {
    unsigned sa = (unsigned)__cvta_generic_to_shared(s);
    asm volatile("cp.async.cg.shared.global [%0], [%1], 16;\n" :: "r"(sa), "l"(g));
}
__device__ __forceinline__ void cpcommit() { asm volatile("cp.async.commit_group;\n"); }
template<int N> __device__ __forceinline__ void cpwait() {
    asm volatile("cp.async.wait_group %0;\n" :: "n"(N));
}

// ---------------- fused conv1 BN-stats + sampled exact conv ----------------
#define ALD 260              // A stage ld: 256 px + 4 pad
#define WLD 36
#define CLD 132
#define STAGE_A (32*ALD)     // 8320 floats
#define STAGE_W (128*WLD)    // 4608 floats
#define NSTAGE 3
#define DYNB (NSTAGE*(STAGE_A+STAGE_W)*4)   // 155136 bytes
#define NSAMPB 64

__global__ __launch_bounds__(512)
void k_fused(const float* __restrict__ feats, const float* __restrict__ W1,
             const float* __restrict__ Wa1,  const int* __restrict__ labels) {
    extern __shared__ float dyn[];
    __shared__ float r1[512], r2[512];
    const int tid = threadIdx.x;

    if (blockIdx.x < NSAMPB) {
        // ============ sampled path: exact fp32 conv at 64 label==1 pixels ============
        const int z = blockIdx.x & 3;        // K-split
        const int b = blockIdx.x >> 2;       // image
        float* Fs  = dyn;                    // [64][33]
        float* Ws2 = dyn + 64*33;            // [192][33]
        int*   pix = (int*)(dyn + 64*33 + 192*33);

        if (tid < 64) pix[tid] = 0;
        __syncthreads();
        if (tid < 32) {
            const int lane = tid;
            int probe = 0;
            #pragma unroll
            for (int i = lane; i < 64; i += 32) probe |= labels[2*(i*512)+1];
            unsigned any = __ballot_sync(0xffffffffu, probe != 0);
            const bool is64 = (any == 0u);
            const long long* L64 = (const long long*)labels;
            int base = 0;
            for (int c = 0; c < 128; c++) {
                if (base >= 64) break;
                int p = (c << 5) + lane;
                long long v = is64 ? L64[(size_t)b*HWN + p]
                                   : (long long)labels[(size_t)b*HWN + p];
                bool valid = (v == 1);
                unsigned m = __ballot_sync(0xffffffffu, valid);
                int pre = __popc(m & ((1u << lane) - 1u));
                if (valid && base + pre < 64) pix[base + pre] = p;
                base += __popc(m);
            }
        }
        __syncthreads();

        float acc[4][6];
        #pragma unroll
        for (int i = 0; i < 4; i++)
            #pragma unroll
            for (int j = 0; j < 6; j++) acc[i][j] = 0.f;

        const int pg = tid & 15;   // 4 pixels each
        const int cg = tid >> 4;   // 6 rows each (32 groups x 6 = 192)
        const size_t fb = (size_t)b*CC*HWN;
        const int kbase = z * 512;

        for (int chn = 0; chn < 16; chn++) {
            int k0 = kbase + chn*32;
            __syncthreads();
            #pragma unroll
            for (int i = 0; i < 4; i++) {
                int idx = tid + i*512;
                int px = idx >> 5, kk = idx & 31;
                Fs[px*33 + kk] = feats[fb + (size_t)(k0+kk)*HWN + pix[px]];
            }
            #pragma unroll
            for (int i = 0; i < 12; i++) {
                int idx = tid + i*512;
                int r = idx >> 5, kk = idx & 31;
                Ws2[r*33 + kk] = (r < 128) ? W1[r*CC + k0 + kk]
                                           : Wa1[(r-128)*CC + k0 + kk];
            }
            __syncthreads();
            #pragma unroll 4
            for (int kk = 0; kk < 32; kk++) {
                float fv[4];
                #pragma unroll
                for (int i = 0; i < 4; i++) fv[i] = Fs[(pg*4 + i)*33 + kk];
                #pragma unroll
                for (int j = 0; j < 6; j++) {
                    float w = Ws2[(cg*6 + j)*33 + kk];
                    #pragma unroll
                    for (int i = 0; i < 4; i++) acc[i][j] += fv[i]*w;
                }
            }
        }
        #pragma unroll
        for (int i = 0; i < 4; i++)
            #pragma unroll
            for (int j = 0; j < 6; j++)
                g_hs4[(size_t)z*196608 + (b*64 + pg*4 + i)*192 + cg*6 + j] = acc[i][j];
        return;
    }

    // ============ conv1 + BN-stats (tf32 WMMA, M=256 x N=128, 3-stage cp.async) =====
    const int cb = blockIdx.x - NSAMPB;
    const int b  = cb >> 4;
    const int p0 = (cb & 15) * 256;
    const float* F = feats + (size_t)b*CC*HWN + p0;

    float* As = dyn;                       // [NSTAGE][32][ALD]
    float* Ws = dyn + NSTAGE*STAGE_A;      // [NSTAGE][128][WLD]

    const int wid = tid >> 5;
    const int wr  = wid & 3;    // 64-pixel group
    const int wc  = wid >> 2;   // 32-channel group

    wmma::fragment<wmma::accumulator,16,16,8,float> acc[4][2];
    #pragma unroll
    for (int i = 0; i < 4; i++)
        #pragma unroll
        for (int j = 0; j < 2; j++) wmma::fill_fragment(acc[i][j], 0.f);

    auto issue = [&](int kc) {
        int s = kc % NSTAGE;
        float* A = As + s*STAGE_A;
        float* W = Ws + s*STAGE_W;
        const float* Fg = F + (size_t)(kc*32)*HWN;
        const float* Wg = W1 + kc*32;
        #pragma unroll
        for (int i = 0; i < 4; i++) {
            int c = tid + i*512;
            int k = c >> 6, px4 = (c & 63) << 2;
            cpasync16(A + k*ALD + px4, Fg + (size_t)k*HWN + px4);
        }
        #pragma unroll
        for (int i = 0; i < 2; i++) {
            int c = tid + i*512;
            int ch = c >> 3, k4 = (c & 7) << 2;
            cpasync16(W + ch*WLD + k4, Wg + ch*CC + k4);
        }
        cpcommit();
    };

    issue(0); issue(1);

    for (int kc = 0; kc < 64; kc++) {
        if (kc + 2 < 64) { issue(kc + 2); cpwait<2>(); }
        else             { cpwait<0>(); }
        __syncthreads();
        const float* Ab = As + (kc % NSTAGE)*STAGE_A;
        const float* Wb = Ws + (kc % NSTAGE)*STAGE_W;
        #pragma unroll
        for (int ks = 0; ks < 32; ks += 8) {
            wmma::fragment<wmma::matrix_a,16,16,8,wmma::precision::tf32,wmma::col_major> af[4];
            #pragma unroll
            for (int i = 0; i < 4; i++) {
                wmma::load_matrix_sync(af[i], Ab + ks*ALD + wr*64 + i*16, ALD);
                #pragma unroll
                for (int e = 0; e < af[i].num_elements; e++)
                    af[i].x[e] = wmma::__float_to_tf32(af[i].x[e]);
            }
            wmma::fragment<wmma::matrix_b,16,16,8,wmma::precision::tf32,wmma::col_major> bf[2];
            #pragma unroll
            for (int j = 0; j < 2; j++) {
                wmma::load_matrix_sync(bf[j], Wb + (wc*32 + j*16)*WLD + ks, WLD);
                #pragma unroll
                for (int e = 0; e < bf[j].num_elements; e++)
                    bf[j].x[e] = wmma::__float_to_tf32(bf[j].x[e]);
            }
            #pragma unroll
            for (int i = 0; i < 4; i++)
                #pragma unroll
                for (int j = 0; j < 2; j++)
                    wmma::mma_sync(acc[i][j], af[i], bf[j], acc[i][j]);
        }
        __syncthreads();
    }

    // Epilogue: C (256 px x 128 ch) -> smem, per-channel sum/sumsq
    float* Cs = dyn;   // 256 x 132 = 33792 floats, fits in dyn
    #pragma unroll
    for (int i = 0; i < 4; i++)
        #pragma unroll
        for (int j = 0; j < 2; j++)
            wmma::store_matrix_sync(Cs + (wr*64 + i*16)*CLD + wc*32 + j*16,
                                    acc[i][j], CLD, wmma::mem_row_major);
    __syncthreads();
    {
        const int ch  = tid & 127;
        const int seg = tid >> 7;          // 4 segments of 64 pixels
        float s = 0.f, s2 = 0.f;
        #pragma unroll 4
        for (int p = seg*64; p < seg*64 + 64; p++) {
            float v = Cs[p*CLD + ch];
            s += v; s2 += v*v;
        }
        r1[tid] = s; r2[tid] = s2;
        __syncthreads();
        if (tid < 128) {
            float ss  = r1[tid] + r1[tid+128] + r1[tid+256] + r1[tid+384];
            float ss2 = r2[tid] + r2[tid+128] + r2[tid+256] + r2[tid+384];
            atomicAdd(&g_sum[tid], ss);
            atomicAdd(&g_sumsq[tid], ss2);
        }
    }
}

// ---------------- per-image: BN apply + conv2 + normalize + attn + contrastive loss ----
// smem float offsets
#define O_W2   0          // 128*132
#define O_XS   16896      // 64*132
#define O_TF   25344      // 64*128
#define O_SIM  33536      // 64*65
#define O_TW   37696      // 64
#define O_DEN  37760      // 64
#define O_RED  37824      // 256
#define PL_DYNB ((38080)*4)

__global__ __launch_bounds__(256) void k_projloss(
        const float* __restrict__ b1, const float* __restrict__ gamma,
        const float* __restrict__ beta, const float* __restrict__ W2,
        const float* __restrict__ b2,  const float* __restrict__ ba1,
        const float* __restrict__ Wa2, const float* __restrict__ ba2) {
    extern __shared__ float sm[];
    float* W2s  = sm + O_W2;
    float* xs   = sm + O_XS;
    float* tf   = sm + O_TF;
    float* simM = sm + O_SIM;
    float* tw   = sm + O_TW;
    float* denom= sm + O_DEN;
    float* red  = sm + O_RED;
    const int t = threadIdx.x;
    const int b = blockIdx.x;

    // stage W2 coalesced
    #pragma unroll
    for (int i = 0; i < 16; i++) {
        int idx = t + i*256;                 // float4 index < 4096
        int o = idx >> 5, c4 = (idx & 31) << 2;
        float4 v = reinterpret_cast<const float4*>(W2)[idx];
        float* d = W2s + o*132 + c4;
        d[0]=v.x; d[1]=v.y; d[2]=v.z; d[3]=v.w;
    }

    // xr = relu(BN(conv1)) at 64 sampled pixels (g_hs4 4-way partials)
    #pragma unroll
    for (int i = 0; i < 32; i++) {
        int idx = t + i*256;                 // < 8192
        int px = idx >> 7, ch = idx & 127;
        int pid = b*64 + px;
        float h = g_hs4[pid*192 + ch] + g_hs4[196608 + pid*192 + ch]
                + g_hs4[2*196608 + pid*192 + ch] + g_hs4[3*196608 + pid*192 + ch]
                + b1[ch];
        float m   = g_sum[ch] * (1.f/65536.f);
        float var = g_sumsq[ch] * (1.f/65536.f) - m*m;
        float xn  = (h - (m + b1[ch])) * rsqrtf(var + 1e-5f) * gamma[ch] + beta[ch];
        xs[px*132 + ch] = fmaxf(xn, 0.f);
    }

    // attention weight per pixel
    {
        const int px = t >> 2, q = t & 3;
        int pid = b*64 + px;
        float part = 0.f;
        #pragma unroll
        for (int c = 0; c < 16; c++) {
            int ch = q*16 + c;
            float ha = g_hs4[pid*192 + 128 + ch] + g_hs4[196608 + pid*192 + 128 + ch]
                     + g_hs4[2*196608 + pid*192 + 128 + ch] + g_hs4[3*196608 + pid*192 + 128 + ch];
            part += fmaxf(ha + ba1[ch], 0.f) * Wa2[ch];
        }
        part += __shfl_xor_sync(0xffffffffu, part, 1);
        part += __shfl_xor_sync(0xffffffffu, part, 2);
        if (q == 0) tw[px] = 1.f / (1.f + expf(-(part + ba2[0])));
    }
    __syncthreads();

    // proj GEMM: out[px][o] = b2[o] + sum_k W2[o][k]*xr[px][k]; L2-normalize per px
    {
        const int px = t >> 2, q = t & 3;
        float acc[32];
        #pragma unroll
        for (int oq = 0; oq < 32; oq++) acc[oq] = b2[q*32 + oq];
        for (int k = 0; k < 128; k++) {
            float xv = xs[px*132 + k];
            #pragma unroll
            for (int oq = 0; oq < 32; oq++)
                acc[oq] += W2s[(q*32 + oq)*132 + k] * xv;
        }
        float s2 = 0.f;
        #pragma unroll
        for (int oq = 0; oq < 32; oq++) s2 += acc[oq]*acc[oq];
        s2 += __shfl_xor_sync(0xffffffffu, s2, 1);
        s2 += __shfl_xor_sync(0xffffffffu, s2, 2);
        float rinv = 1.f / fmaxf(sqrtf(s2), 1e-12f);
        #pragma unroll
        for (int oq = 0; oq < 32; oq++)
            tf[px*128 + q*32 + oq] = acc[oq] * rinv;
    }
    __syncthreads();

    // sim = tf @ tf^T / T ; parallel denominators
    const int i  = t >> 2;
    const int j0 = (t & 3) << 4;
    {
        float acc[16];
        #pragma unroll
        for (int j = 0; j < 16; j++) acc[j] = 0.f;
        const float4* fi = reinterpret_cast<const float4*>(tf + i*128);
        #pragma unroll 4
        for (int k4 = 0; k4 < 32; k4++) {
            float4 a = fi[k4];
            #pragma unroll
            for (int j = 0; j < 16; j++) {
                float4 c = reinterpret_cast<const float4*>(tf + (j0 + j)*128)[k4];
                acc[j] += a.x*c.x + a.y*c.y + a.z*c.z + a.w*c.w;
            }
        }
        float dpart = 0.f;
        #pragma unroll
        for (int j = 0; j < 16; j++) {
            float s = acc[j] * 10.f;
            simM[i*65 + j0 + j] = s;
            dpart += expf(s);
        }
        dpart += __shfl_xor_sync(0xffffffffu, dpart, 1);
        dpart += __shfl_xor_sync(0xffffffffu, dpart, 2);
        if ((t & 3) == 0) denom[i] = dpart;
    }
    __syncthreads();

    // weighted log-prob over positive pairs
    {
        float lacc = 0.f;
        float di  = denom[i];
        float twi = tw[i];
        #pragma unroll
        for (int j = 0; j < 16; j++) {
            int jj = j0 + j;
            float s = simM[i*65 + jj];
            if (s > 0.7f && jj != i) {
                float lp = logf(expf(s)/di + 1e-10f);
                lacc += twi * tw[jj] * lp;
            }
        }
        red[t] = lacc;
    }
    __syncthreads();
    for (int sft = 128; sft > 0; sft >>= 1) { if (t < sft) red[t] += red[t+sft]; __syncthreads(); }
    if (t == 0) {
        float tsum = 0.f;
        for (int j = 0; j < 64; j++) tsum += tw[j];
        g_loss[b] = -(0.1f/0.07f) * red[0] / tsum;
    }
}

// ---------------- final mean * LOSS_WEIGHT ----------------
__global__ void k_final(float* out) {
    int t = threadIdx.x;
    float v = (t < 16) ? g_loss[t] : 0.f;
    #pragma unroll
    for (int o = 16; o > 0; o >>= 1) v += __shfl_down_sync(0xffffffffu, v, o);
    if (t == 0) out[0] = (v / 16.0f) * 0.1f;
}

// ---------------- launch ----------------
extern "C" void kernel_launch(void* const* d_in, const int* in_sizes, int n_in,
                              void* d_out, int out_size) {
    const float* feats = (const float*)d_in[0];
    const int*   labels= (const int*)d_in[1];
    const float* W1   = (const float*)d_in[2];
    const float* b1   = (const float*)d_in[3];
    const float* gamma= (const float*)d_in[4];
    const float* beta = (const float*)d_in[5];
    const float* W2   = (const float*)d_in[6];
    const float* b2   = (const float*)d_in[7];
    const float* Wa1  = (const float*)d_in[8];
    const float* ba1  = (const float*)d_in[9];
    const float* Wa2  = (const float*)d_in[10];
    const float* ba2  = (const float*)d_in[11];

    cudaFuncSetAttribute(k_fused, cudaFuncAttributeMaxDynamicSharedMemorySize, DYNB);
    cudaFuncSetAttribute(k_projloss, cudaFuncAttributeMaxDynamicSharedMemorySize, PL_DYNB);

    k_init0<<<1, 128>>>();
    k_fused<<<NSAMPB + 256, 512, DYNB>>>(feats, W1, Wa1, labels);
    k_projloss<<<16, 256, PL_DYNB>>>(b1, gamma, beta, W2, b2, ba1, Wa2, ba2);
    k_final<<<1, 32>>>((float*)d_out);
}

// round 5
// speedup vs baseline: 1.6401x; 1.6401x over previous
#include <cuda_runtime.h>
#include <cuda_bf16.h>
#include <mma.h>
#include <cstdint>

using namespace nvcuda;

#define CC 2048
#define HWN 4096
#define NCONVB 256
#define NSAMPB 64

// ---------------- device scratch ----------------
__device__ float g_sum[128];
__device__ float g_sumsq[128];
__device__ float g_hs4[4*1024*192];   // 4 K-splits of sampled raw dot products
__device__ float g_loss[16];

__global__ void k_init0() {
    int t = threadIdx.x;
    if (t < 128) { g_sum[t] = 0.f; g_sumsq[t] = 0.f; }
}

// ---------------- cp.async helpers ----------------
__device__ __forceinline__ void cpasync16(void* s, const void* g) {
    unsigned sa = (unsigned)__cvta_generic_to_shared(s);
    asm volatile("cp.async.cg.shared.global [%0], [%1], 16;\n" :: "r"(sa), "l"(g));
}
__device__ __forceinline__ void cpcommit() { asm volatile("cp.async.commit_group;\n"); }
template<int N> __device__ __forceinline__ void cpwait() {
    asm volatile("cp.async.wait_group %0;\n" :: "n"(N));
}
__device__ __forceinline__ uint32_t bf2(float x, float y) {
    __nv_bfloat162 h = __floats2bfloat162_rn(x, y);
    return *reinterpret_cast<uint32_t*>(&h);
}

// ---------------- smem layout (bytes) ----------------
// fp32 stages: A 3 x [16][256] f32 = 49152 ; W 3 x [128][16] f32 = 24576
// bf16 bufs : A 3 x [16][264] bf16 = 25344 ; W 3 x [128][24] bf16 = 18432
#define OF_AF 0
#define OF_WF 49152
#define OF_AB 73728
#define OF_WB 99072
#define AF_STAGE 16384
#define WF_STAGE 8192
#define AB_STAGE 8448
#define WB_STAGE 6144
#define DYNB 139264        // >= Cs reuse: 256*132*4 = 135168

__global__ __launch_bounds__(512)
void k_fused(const float* __restrict__ feats, const float* __restrict__ W1,
             const float* __restrict__ Wa1,  const int* __restrict__ labels) {
    extern __shared__ char dynC[];
    float* dyn = (float*)dynC;
    __shared__ float r1[512], r2[512];
    const int tid = threadIdx.x;

    if (blockIdx.x >= NCONVB) {
        // ============ sampled path: exact fp32 conv at 64 label==1 pixels ============
        const int sb = blockIdx.x - NCONVB;
        const int z = sb & 3;        // K-split
        const int b = sb >> 2;       // image
        float* Fs  = dyn;                    // [64][33]
        float* Ws2 = dyn + 64*33;            // [192][33]
        int*   pix = (int*)(dyn + 64*33 + 192*33);

        if (tid < 64) pix[tid] = 0;
        __syncthreads();
        if (tid < 32) {
            const int lane = tid;
            int probe = 0;
            #pragma unroll
            for (int i = lane; i < 64; i += 32) probe |= labels[2*(i*512)+1];
            unsigned any = __ballot_sync(0xffffffffu, probe != 0);
            const bool is64 = (any == 0u);
            const long long* L64 = (const long long*)labels;
            int base = 0;
            for (int c = 0; c < 128; c++) {
                if (base >= 64) break;
                int p = (c << 5) + lane;
                long long v = is64 ? L64[(size_t)b*HWN + p]
                                   : (long long)labels[(size_t)b*HWN + p];
                bool valid = (v == 1);
                unsigned m = __ballot_sync(0xffffffffu, valid);
                int pre = __popc(m & ((1u << lane) - 1u));
                if (valid && base + pre < 64) pix[base + pre] = p;
                base += __popc(m);
            }
        }
        __syncthreads();

        float acc[4][6];
        #pragma unroll
        for (int i = 0; i < 4; i++)
            #pragma unroll
            for (int j = 0; j < 6; j++) acc[i][j] = 0.f;

        const int pg = tid & 15;   // 4 pixels each
        const int cg = tid >> 4;   // 6 rows each (32 groups x 6 = 192)
        const size_t fb = (size_t)b*CC*HWN;
        const int kbase = z * 512;

        for (int chn = 0; chn < 16; chn++) {
            int k0 = kbase + chn*32;
            __syncthreads();
            #pragma unroll
            for (int i = 0; i < 4; i++) {
                int idx = tid + i*512;
                int px = idx >> 5, kk = idx & 31;
                Fs[px*33 + kk] = feats[fb + (size_t)(k0+kk)*HWN + pix[px]];
            }
            #pragma unroll
            for (int i = 0; i < 12; i++) {
                int idx = tid + i*512;
                int r = idx >> 5, kk = idx & 31;
                Ws2[r*33 + kk] = (r < 128) ? W1[r*CC + k0 + kk]
                                           : Wa1[(r-128)*CC + k0 + kk];
            }
            __syncthreads();
            #pragma unroll 4
            for (int kk = 0; kk < 32; kk++) {
                float fv[4];
                #pragma unroll
                for (int i = 0; i < 4; i++) fv[i] = Fs[(pg*4 + i)*33 + kk];
                #pragma unroll
                for (int j = 0; j < 6; j++) {
                    float w = Ws2[(cg*6 + j)*33 + kk];
                    #pragma unroll
                    for (int i = 0; i < 4; i++) acc[i][j] += fv[i]*w;
                }
            }
        }
        #pragma unroll
        for (int i = 0; i < 4; i++)
            #pragma unroll
            for (int j = 0; j < 6; j++)
                g_hs4[(size_t)z*196608 + (b*64 + pg*4 + i)*192 + cg*6 + j] = acc[i][j];
        return;
    }

    // ============ conv1 + BN-stats: bf16 wmma, M=256 x N=128, K-chunk 16 ============
    const int cb = blockIdx.x;
    const int b  = cb >> 4;
    const int p0 = (cb & 15) * 256;
    const float* F = feats + (size_t)b*CC*HWN + p0;

    const int wid = tid >> 5;
    const int wr  = wid & 3;    // 64-pixel group
    const int wc  = wid >> 2;   // 32-channel group

    wmma::fragment<wmma::accumulator,16,16,16,float> acc[4][2];
    #pragma unroll
    for (int i = 0; i < 4; i++)
        #pragma unroll
        for (int j = 0; j < 2; j++) wmma::fill_fragment(acc[i][j], 0.f);

    auto issue = [&](int kc) {
        if (kc >= 128) return;
        float* Af = dyn + (OF_AF/4) + (kc % 3)*(AF_STAGE/4);
        float* Wf = dyn + (OF_WF/4) + (kc % 3)*(WF_STAGE/4);
        const float* Fg = F + (size_t)(kc*16)*HWN;
        #pragma unroll
        for (int i = 0; i < 2; i++) {
            int idx = tid + i*512;
            int k = idx >> 6, px4 = (idx & 63) << 2;
            cpasync16(Af + k*256 + px4, Fg + (size_t)k*HWN + px4);
        }
        {
            int ch = tid >> 2, k4 = (tid & 3) << 2;
            cpasync16(Wf + ch*16 + k4, W1 + ch*CC + kc*16 + k4);
        }
        cpcommit();
    };
    auto convert = [&](int kc) {
        float* Af = dyn + (OF_AF/4) + (kc % 3)*(AF_STAGE/4);
        float* Wf = dyn + (OF_WF/4) + (kc % 3)*(WF_STAGE/4);
        char* Ab = dynC + OF_AB + (kc % 3)*AB_STAGE;
        char* Wb = dynC + OF_WB + (kc % 3)*WB_STAGE;
        #pragma unroll
        for (int i = 0; i < 2; i++) {
            int idx = tid + i*512;
            int k = idx >> 6, px4 = (idx & 63) << 2;
            float4 v = *reinterpret_cast<float4*>(Af + k*256 + px4);
            uint2 u; u.x = bf2(v.x, v.y); u.y = bf2(v.z, v.w);
            *reinterpret_cast<uint2*>(Ab + (k*264 + px4)*2) = u;
        }
        {
            int ch = tid >> 2, k4 = (tid & 3) << 2;
            float4 v = *reinterpret_cast<float4*>(Wf + ch*16 + k4);
            uint2 u; u.x = bf2(v.x, v.y); u.y = bf2(v.z, v.w);
            *reinterpret_cast<uint2*>(Wb + (ch*24 + k4)*2) = u;
        }
    };
    auto compute = [&](int kc) {
        const __nv_bfloat16* Ab = (const __nv_bfloat16*)(dynC + OF_AB + (kc % 3)*AB_STAGE);
        const __nv_bfloat16* Wb = (const __nv_bfloat16*)(dynC + OF_WB + (kc % 3)*WB_STAGE);
        wmma::fragment<wmma::matrix_a,16,16,16,__nv_bfloat16,wmma::col_major> af[4];
        #pragma unroll
        for (int i = 0; i < 4; i++)
            wmma::load_matrix_sync(af[i], Ab + wr*64 + i*16, 264);
        wmma::fragment<wmma::matrix_b,16,16,16,__nv_bfloat16,wmma::col_major> bf[2];
        #pragma unroll
        for (int j = 0; j < 2; j++)
            wmma::load_matrix_sync(bf[j], Wb + (wc*32 + j*16)*24, 24);
        #pragma unroll
        for (int i = 0; i < 4; i++)
            #pragma unroll
            for (int j = 0; j < 2; j++)
                wmma::mma_sync(acc[i][j], af[i], bf[j], acc[i][j]);
    };

    // prologue
    issue(0); issue(1);
    cpwait<1>();
    __syncthreads();
    convert(0);
    issue(2);

    for (int kc = 0; kc < 128; kc++) {
        if (kc < 127) {
            if (kc + 2 < 128) cpwait<1>(); else cpwait<0>();
        }
        __syncthreads();
        if (kc < 127) { convert(kc + 1); issue(kc + 3); }
        compute(kc);
    }
    __syncthreads();

    // Epilogue: C (256 px x 128 ch) -> smem, per-channel sum/sumsq
    float* Cs = dyn;   // 256 x 132 fp32
    #pragma unroll
    for (int i = 0; i < 4; i++)
        #pragma unroll
        for (int j = 0; j < 2; j++)
            wmma::store_matrix_sync(Cs + (wr*64 + i*16)*132 + wc*32 + j*16,
                                    acc[i][j], 132, wmma::mem_row_major);
    __syncthreads();
    {
        const int ch  = tid & 127;
        const int seg = tid >> 7;          // 4 segments of 64 pixels
        float s = 0.f, s2 = 0.f;
        #pragma unroll 4
        for (int p = seg*64; p < seg*64 + 64; p++) {
            float v = Cs[p*132 + ch];
            s += v; s2 += v*v;
        }
        r1[tid] = s; r2[tid] = s2;
        __syncthreads();
        if (tid < 128) {
            float ss  = r1[tid] + r1[tid+128] + r1[tid+256] + r1[tid+384];
            float ss2 = r2[tid] + r2[tid+128] + r2[tid+256] + r2[tid+384];
            atomicAdd(&g_sum[tid], ss);
            atomicAdd(&g_sumsq[tid], ss2);
        }
    }
}

// ---------------- per-image: BN apply + conv2 + normalize + attn + contrastive loss ----
#define O_W2   0
#define O_XS   16896
#define O_TF   25344
#define O_SIM  33536
#define O_TW   37696
#define O_DEN  37760
#define O_RED  37824
#define PL_DYNB ((38080)*4)

__global__ __launch_bounds__(256) void k_projloss(
        const float* __restrict__ b1, const float* __restrict__ gamma,
        const float* __restrict__ beta, const float* __restrict__ W2,
        const float* __restrict__ b2,  const float* __restrict__ ba1,
        const float* __restrict__ Wa2, const float* __restrict__ ba2) {
    extern __shared__ float sm[];
    float* W2s  = sm + O_W2;
    float* xs   = sm + O_XS;
    float* tf   = sm + O_TF;
    float* simM = sm + O_SIM;
    float* tw   = sm + O_TW;
    float* denom= sm + O_DEN;
    float* red  = sm + O_RED;
    const int t = threadIdx.x;
    const int b = blockIdx.x;

    #pragma unroll
    for (int i = 0; i < 16; i++) {
        int idx = t + i*256;
        int o = idx >> 5, c4 = (idx & 31) << 2;
        float4 v = reinterpret_cast<const float4*>(W2)[idx];
        float* d = W2s + o*132 + c4;
        d[0]=v.x; d[1]=v.y; d[2]=v.z; d[3]=v.w;
    }

    #pragma unroll
    for (int i = 0; i < 32; i++) {
        int idx = t + i*256;
        int px = idx >> 7, ch = idx & 127;
        int pid = b*64 + px;
        float h = g_hs4[pid*192 + ch] + g_hs4[196608 + pid*192 + ch]
                + g_hs4[2*196608 + pid*192 + ch] + g_hs4[3*196608 + pid*192 + ch]
                + b1[ch];
        float m   = g_sum[ch] * (1.f/65536.f);
        float var = g_sumsq[ch] * (1.f/65536.f) - m*m;
        float xn  = (h - (m + b1[ch])) * rsqrtf(var + 1e-5f) * gamma[ch] + beta[ch];
        xs[px*132 + ch] = fmaxf(xn, 0.f);
    }

    {
        const int px = t >> 2, q = t & 3;
        int pid = b*64 + px;
        float part = 0.f;
        #pragma unroll
        for (int c = 0; c < 16; c++) {
            int ch = q*16 + c;
            float ha = g_hs4[pid*192 + 128 + ch] + g_hs4[196608 + pid*192 + 128 + ch]
                     + g_hs4[2*196608 + pid*192 + 128 + ch] + g_hs4[3*196608 + pid*192 + 128 + ch];
            part += fmaxf(ha + ba1[ch], 0.f) * Wa2[ch];
        }
        part += __shfl_xor_sync(0xffffffffu, part, 1);
        part += __shfl_xor_sync(0xffffffffu, part, 2);
        if (q == 0) tw[px] = 1.f / (1.f + expf(-(part + ba2[0])));
    }
    __syncthreads();

    {
        const int px = t >> 2, q = t & 3;
        float acc[32];
        #pragma unroll
        for (int oq = 0; oq < 32; oq++) acc[oq] = b2[q*32 + oq];
        for (int k = 0; k < 128; k++) {
            float xv = xs[px*132 + k];
            #pragma unroll
            for (int oq = 0; oq < 32; oq++)
                acc[oq] += W2s[(q*32 + oq)*132 + k] * xv;
        }
        float s2 = 0.f;
        #pragma unroll
        for (int oq = 0; oq < 32; oq++) s2 += acc[oq]*acc[oq];
        s2 += __shfl_xor_sync(0xffffffffu, s2, 1);
        s2 += __shfl_xor_sync(0xffffffffu, s2, 2);
        float rinv = 1.f / fmaxf(sqrtf(s2), 1e-12f);
        #pragma unroll
        for (int oq = 0; oq < 32; oq++)
            tf[px*128 + q*32 + oq] = acc[oq] * rinv;
    }
    __syncthreads();

    const int i  = t >> 2;
    const int j0 = (t & 3) << 4;
    {
        float acc[16];
        #pragma unroll
        for (int j = 0; j < 16; j++) acc[j] = 0.f;
        const float4* fi = reinterpret_cast<const float4*>(tf + i*128);
        #pragma unroll 4
        for (int k4 = 0; k4 < 32; k4++) {
            float4 a = fi[k4];
            #pragma unroll
            for (int j = 0; j < 16; j++) {
                float4 c = reinterpret_cast<const float4*>(tf + (j0 + j)*128)[k4];
                acc[j] += a.x*c.x + a.y*c.y + a.z*c.z + a.w*c.w;
            }
        }
        float dpart = 0.f;
        #pragma unroll
        for (int j = 0; j < 16; j++) {
            float s = acc[j] * 10.f;
            simM[i*65 + j0 + j] = s;
            dpart += expf(s);
        }
        dpart += __shfl_xor_sync(0xffffffffu, dpart, 1);
        dpart += __shfl_xor_sync(0xffffffffu, dpart, 2);
        if ((t & 3) == 0) denom[i] = dpart;
    }
    __syncthreads();

    {
        float lacc = 0.f;
        float di  = denom[i];
        float twi = tw[i];
        #pragma unroll
        for (int j = 0; j < 16; j++) {
            int jj = j0 + j;
            float s = simM[i*65 + jj];
            if (s > 0.7f && jj != i) {
                float lp = logf(expf(s)/di + 1e-10f);
                lacc += twi * tw[jj] * lp;
            }
        }
        red[t] = lacc;
    }
    __syncthreads();
    for (int sft = 128; sft > 0; sft >>= 1) { if (t < sft) red[t] += red[t+sft]; __syncthreads(); }
    if (t == 0) {
        float tsum = 0.f;
        for (int j = 0; j < 64; j++) tsum += tw[j];
        g_loss[b] = -(0.1f/0.07f) * red[0] / tsum;
    }
}

// ---------------- final mean * LOSS_WEIGHT ----------------
__global__ void k_final(float* out) {
    int t = threadIdx.x;
    float v = (t < 16) ? g_loss[t] : 0.f;
    #pragma unroll
    for (int o = 16; o > 0; o >>= 1) v += __shfl_down_sync(0xffffffffu, v, o);
    if (t == 0) out[0] = (v / 16.0f) * 0.1f;
}

// ---------------- launch ----------------
extern "C" void kernel_launch(void* const* d_in, const int* in_sizes, int n_in,
                              void* d_out, int out_size) {
    const float* feats = (const float*)d_in[0];
    const int*   labels= (const int*)d_in[1];
    const float* W1   = (const float*)d_in[2];
    const float* b1   = (const float*)d_in[3];
    const float* gamma= (const float*)d_in[4];
    const float* beta = (const float*)d_in[5];
    const float* W2   = (const float*)d_in[6];
    const float* b2   = (const float*)d_in[7];
    const float* Wa1  = (const float*)d_in[8];
    const float* ba1  = (const float*)d_in[9];
    const float* Wa2  = (const float*)d_in[10];
    const float* ba2  = (const float*)d_in[11];

    cudaFuncSetAttribute(k_fused, cudaFuncAttributeMaxDynamicSharedMemorySize, DYNB);
    cudaFuncSetAttribute(k_projloss, cudaFuncAttributeMaxDynamicSharedMemorySize, PL_DYNB);

    k_init0<<<1, 128>>>();
    k_fused<<<NCONVB + NSAMPB, 512, DYNB>>>(feats, W1, Wa1, labels);
    k_projloss<<<16, 256, PL_DYNB>>>(b1, gamma, beta, W2, b2, ba1, Wa2, ba2);
    k_final<<<1, 32>>>((float*)d_out);
}

// round 6
// speedup vs baseline: 1.7105x; 1.0429x over previous
#include <cuda_runtime.h>
#include <cuda_fp16.h>
#include <mma.h>
#include <cstdint>

using namespace nvcuda;

#define CC 2048
#define HWN 4096
#define NCONVB 512
#define NSAMPB 128   // 16 img x 8 K-splits

// ---------------- device scratch ----------------
__device__ float g_p1[NCONVB*128];
__device__ float g_p2[NCONVB*128];
__device__ float g_hs8[8*1024*192];
__device__ float g_loss[16];

// ---------------- helpers ----------------
__device__ __forceinline__ void cpasync16(void* s, const void* g) {
    unsigned sa = (unsigned)__cvta_generic_to_shared(s);
    asm volatile("cp.async.cg.shared.global [%0], [%1], 16;\n" :: "r"(sa), "l"(g));
}
__device__ __forceinline__ void cpcommit() { asm volatile("cp.async.commit_group;\n"); }
template<int N> __device__ __forceinline__ void cpwait() {
    asm volatile("cp.async.wait_group %0;\n" :: "n"(N));
}
__device__ __forceinline__ uint32_t h2u(float x, float y) {
    __half2 h = __floats2half2_rn(x, y);
    return *reinterpret_cast<uint32_t*>(&h);
}

// smem layout (bytes): fp32 A 2x16896 | fp32 W 2x18432 | f16 A 2x8704 | f16 W 2x10240
#define DYNB 108544

__global__ __launch_bounds__(256, 2)
void k_fused(const float* __restrict__ feats, const float* __restrict__ W1,
             const float* __restrict__ Wa1,  const int* __restrict__ labels) {
    extern __shared__ char dynC[];
    float* dyn = (float*)dynC;
    __shared__ float r1[256], r2[256];
    const int tid = threadIdx.x;

    if (blockIdx.x >= NCONVB) {
        // ============ sampled path: exact fp32 conv at 64 label==1 pixels ============
        const int sb = blockIdx.x - NCONVB;
        const int z = sb & 7;        // K-split (256 channels each)
        const int b = sb >> 3;       // image
        float* Fs  = dyn;                    // [64][33]
        float* Ws2 = dyn + 64*33;            // [192][33]
        int*   pix = (int*)(dyn + 64*33 + 192*33);

        if (tid < 64) pix[tid] = 0;
        __syncthreads();
        if (tid < 32) {
            const int lane = tid;
            int probe = 0;
            #pragma unroll
            for (int i = lane; i < 64; i += 32) probe |= labels[2*(i*512)+1];
            unsigned any = __ballot_sync(0xffffffffu, probe != 0);
            const bool is64 = (any == 0u);
            const long long* L64 = (const long long*)labels;
            int base = 0;
            for (int c = 0; c < 128; c++) {
                if (base >= 64) break;
                int p = (c << 5) + lane;
                long long v = is64 ? L64[(size_t)b*HWN + p]
                                   : (long long)labels[(size_t)b*HWN + p];
                bool valid = (v == 1);
                unsigned m = __ballot_sync(0xffffffffu, valid);
                int pre = __popc(m & ((1u << lane) - 1u));
                if (valid && base + pre < 64) pix[base + pre] = p;
                base += __popc(m);
            }
        }
        __syncthreads();

        float acc[4][12];
        #pragma unroll
        for (int i = 0; i < 4; i++)
            #pragma unroll
            for (int j = 0; j < 12; j++) acc[i][j] = 0.f;

        const int pg = tid & 15;   // 4 pixels each
        const int cg = tid >> 4;   // 12 rows each (16 groups x 12 = 192)
        const size_t fb = (size_t)b*CC*HWN;
        const int kbase = z * 256;

        for (int chn = 0; chn < 8; chn++) {
            int k0 = kbase + chn*32;
            __syncthreads();
            #pragma unroll
            for (int i = 0; i < 8; i++) {
                int idx = tid + i*256;
                int px = idx >> 5, kk = idx & 31;
                Fs[px*33 + kk] = feats[fb + (size_t)(k0+kk)*HWN + pix[px]];
            }
            #pragma unroll
            for (int i = 0; i < 24; i++) {
                int idx = tid + i*256;
                int r = idx >> 5, kk = idx & 31;
                Ws2[r*33 + kk] = (r < 128) ? W1[r*CC + k0 + kk]
                                           : Wa1[(r-128)*CC + k0 + kk];
            }
            __syncthreads();
            #pragma unroll 4
            for (int kk = 0; kk < 32; kk++) {
                float fv[4];
                #pragma unroll
                for (int i = 0; i < 4; i++) fv[i] = Fs[(pg*4 + i)*33 + kk];
                #pragma unroll
                for (int j = 0; j < 12; j++) {
                    float w = Ws2[(cg*12 + j)*33 + kk];
                    #pragma unroll
                    for (int i = 0; i < 4; i++) acc[i][j] += fv[i]*w;
                }
            }
        }
        #pragma unroll
        for (int i = 0; i < 4; i++)
            #pragma unroll
            for (int j = 0; j < 12; j++)
                g_hs8[(size_t)z*196608 + (b*64 + pg*4 + i)*192 + cg*12 + j] = acc[i][j];
        return;
    }

    // ============ conv1 stats: f16 wmma (f16 accum), M=128 x N=128, K-chunk 32 =======
    const int cb = blockIdx.x;
    const int b  = cb >> 5;
    const int p0 = (cb & 31) * 128;
    const float* F = feats + (size_t)b*CC*HWN + p0;

    const int wid = tid >> 5;
    const int wr  = wid & 3;    // 32-pixel group
    const int wc  = wid >> 2;   // 64-channel group

    wmma::fragment<wmma::accumulator,16,16,16,half> acc[2][4];
    #pragma unroll
    for (int i = 0; i < 2; i++)
        #pragma unroll
        for (int j = 0; j < 4; j++) wmma::fill_fragment(acc[i][j], __float2half(0.f));

    auto Af = [&](int s) { return dyn + s*4224; };                       // [32k][132]
    auto Wf = [&](int s) { return dyn + 8448 + s*4608; };                // [128ch][36]
    auto Ah = [&](int s) { return (half*)(dynC + 70656 + s*8704); };     // [32k][136]
    auto Wh = [&](int s) { return (half*)(dynC + 88064 + s*10240); };    // [128ch][40]

    auto issue = [&](int kc) {
        float* A = Af(kc & 1);
        float* W = Wf(kc & 1);
        const float* Fg = F + (size_t)(kc*32)*HWN;
        const float* Wg = W1 + kc*32;
        #pragma unroll
        for (int i = 0; i < 4; i++) {
            int idx = tid + i*256;
            int k = idx >> 5, px4 = (idx & 31) << 2;
            cpasync16(A + k*132 + px4, Fg + (size_t)k*HWN + px4);
        }
        #pragma unroll
        for (int i = 0; i < 4; i++) {
            int idx = tid + i*256;
            int ch = idx >> 3, k4 = (idx & 7) << 2;
            cpasync16(W + ch*36 + k4, Wg + ch*CC + k4);
        }
        cpcommit();
    };
    auto convert = [&](int kc) {
        float* A = Af(kc & 1);
        float* W = Wf(kc & 1);
        half* Ab = Ah(kc & 1);
        half* Wb = Wh(kc & 1);
        #pragma unroll
        for (int i = 0; i < 4; i++) {
            int idx = tid + i*256;
            int k = idx >> 5, px4 = (idx & 31) << 2;
            float4 v = *reinterpret_cast<float4*>(A + k*132 + px4);
            uint2 u; u.x = h2u(v.x, v.y); u.y = h2u(v.z, v.w);
            *reinterpret_cast<uint2*>(Ab + k*136 + px4) = u;
        }
        #pragma unroll
        for (int i = 0; i < 4; i++) {
            int idx = tid + i*256;
            int ch = idx >> 3, k4 = (idx & 7) << 2;
            float4 v = *reinterpret_cast<float4*>(W + ch*36 + k4);
            uint2 u; u.x = h2u(v.x, v.y); u.y = h2u(v.z, v.w);
            *reinterpret_cast<uint2*>(Wb + ch*40 + k4) = u;
        }
    };
    auto compute = [&](int kc) {
        const half* Ab = Ah(kc & 1);
        const half* Wb = Wh(kc & 1);
        #pragma unroll
        for (int ks = 0; ks < 32; ks += 16) {
            wmma::fragment<wmma::matrix_a,16,16,16,half,wmma::col_major> af[2];
            #pragma unroll
            for (int i = 0; i < 2; i++)
                wmma::load_matrix_sync(af[i], Ab + ks*136 + wr*32 + i*16, 136);
            wmma::fragment<wmma::matrix_b,16,16,16,half,wmma::col_major> bf[4];
            #pragma unroll
            for (int j = 0; j < 4; j++)
                wmma::load_matrix_sync(bf[j], Wb + (wc*64 + j*16)*40 + ks, 40);
            #pragma unroll
            for (int i = 0; i < 2; i++)
                #pragma unroll
                for (int j = 0; j < 4; j++)
                    wmma::mma_sync(acc[i][j], af[i], bf[j], acc[i][j]);
        }
    };

    issue(0); issue(1);

    for (int kc = 0; kc < 64; kc++) {
        if (kc < 62) cpwait<1>(); else cpwait<0>();
        __syncthreads();
        convert(kc);
        __syncthreads();
        if (kc + 2 < 64) issue(kc + 2);
        compute(kc);
    }
    __syncthreads();

    // Epilogue: acc (f16) -> smem -> per-channel sum/sumsq over 128 pixels
    half* Cs16 = (half*)dynC;   // [128 px][136]
    #pragma unroll
    for (int i = 0; i < 2; i++)
        #pragma unroll
        for (int j = 0; j < 4; j++)
            wmma::store_matrix_sync(Cs16 + (wr*32 + i*16)*136 + wc*64 + j*16,
                                    acc[i][j], 136, wmma::mem_row_major);
    __syncthreads();
    {
        const int ch = tid & 127;
        const int sg = tid >> 7;       // 2 segments of 64 pixels
        float s = 0.f, s2 = 0.f;
        #pragma unroll 4
        for (int p = sg*64; p < sg*64 + 64; p++) {
            float v = __half2float(Cs16[p*136 + ch]);
            s += v; s2 += v*v;
        }
        r1[tid] = s; r2[tid] = s2;
        __syncthreads();
        if (tid < 128) {
            g_p1[cb*128 + tid] = r1[tid] + r1[tid+128];
            g_p2[cb*128 + tid] = r2[tid] + r2[tid+128];
        }
    }
}

// ---------------- per-image: stats reduce + BN + conv2 + normalize + attn + loss -------
#define O_W2   0
#define O_XS   16896
#define O_TF   25344
#define O_SIM  33536
#define O_TW   37696
#define O_DEN  37760
#define O_RED  37824
#define O_MEAN 38080
#define O_ISTD 38208
#define O_RS   38336
#define O_RS2  38592
#define PL_DYNB (38848*4)

__global__ __launch_bounds__(256) void k_projloss(
        const float* __restrict__ b1, const float* __restrict__ gamma,
        const float* __restrict__ beta, const float* __restrict__ W2,
        const float* __restrict__ b2,  const float* __restrict__ ba1,
        const float* __restrict__ Wa2, const float* __restrict__ ba2) {
    extern __shared__ float sm[];
    float* W2s  = sm + O_W2;
    float* xs   = sm + O_XS;
    float* tf   = sm + O_TF;
    float* simM = sm + O_SIM;
    float* tw   = sm + O_TW;
    float* denom= sm + O_DEN;
    float* red  = sm + O_RED;
    float* smean= sm + O_MEAN;
    float* sistd= sm + O_ISTD;
    float* rS   = sm + O_RS;
    float* rS2  = sm + O_RS2;
    const int t = threadIdx.x;
    const int b = blockIdx.x;

    // reduce per-block conv partials -> mean / istd
    {
        int ch = t & 127, sg = t >> 7;
        float S = 0.f, S2 = 0.f;
        #pragma unroll 4
        for (int i = sg*256; i < sg*256 + 256; i++) {
            S  += g_p1[i*128 + ch];
            S2 += g_p2[i*128 + ch];
        }
        rS[t] = S; rS2[t] = S2;
    }
    __syncthreads();
    if (t < 128) {
        float S  = rS[t]  + rS[t+128];
        float S2 = rS2[t] + rS2[t+128];
        float m   = S  * (1.f/65536.f);
        float var = S2 * (1.f/65536.f) - m*m;
        smean[t] = m;
        sistd[t] = rsqrtf(var + 1e-5f);
    }

    // stage W2 coalesced
    #pragma unroll
    for (int i = 0; i < 16; i++) {
        int idx = t + i*256;
        int o = idx >> 5, c4 = (idx & 31) << 2;
        float4 v = reinterpret_cast<const float4*>(W2)[idx];
        float* d = W2s + o*132 + c4;
        d[0]=v.x; d[1]=v.y; d[2]=v.z; d[3]=v.w;
    }
    __syncthreads();

    // xr = relu(BN(conv1)) at sampled pixels (8-way partials)
    #pragma unroll
    for (int i = 0; i < 32; i++) {
        int idx = t + i*256;
        int px = idx >> 7, ch = idx & 127;
        int pid = b*64 + px;
        float h = b1[ch];
        #pragma unroll
        for (int z = 0; z < 8; z++) h += g_hs8[(size_t)z*196608 + pid*192 + ch];
        float xn = (h - (smean[ch] + b1[ch])) * sistd[ch] * gamma[ch] + beta[ch];
        xs[px*132 + ch] = fmaxf(xn, 0.f);
    }

    // attention weight per pixel
    {
        const int px = t >> 2, q = t & 3;
        int pid = b*64 + px;
        float part = 0.f;
        #pragma unroll
        for (int c = 0; c < 16; c++) {
            int ch = q*16 + c;
            float ha = 0.f;
            #pragma unroll
            for (int z = 0; z < 8; z++) ha += g_hs8[(size_t)z*196608 + pid*192 + 128 + ch];
            part += fmaxf(ha + ba1[ch], 0.f) * Wa2[ch];
        }
        part += __shfl_xor_sync(0xffffffffu, part, 1);
        part += __shfl_xor_sync(0xffffffffu, part, 2);
        if (q == 0) tw[px] = 1.f / (1.f + expf(-(part + ba2[0])));
    }
    __syncthreads();

    // proj GEMM + L2 normalize
    {
        const int px = t >> 2, q = t & 3;
        float acc[32];
        #pragma unroll
        for (int oq = 0; oq < 32; oq++) acc[oq] = b2[q*32 + oq];
        for (int k = 0; k < 128; k++) {
            float xv = xs[px*132 + k];
            #pragma unroll
            for (int oq = 0; oq < 32; oq++)
                acc[oq] += W2s[(q*32 + oq)*132 + k] * xv;
        }
        float s2 = 0.f;
        #pragma unroll
        for (int oq = 0; oq < 32; oq++) s2 += acc[oq]*acc[oq];
        s2 += __shfl_xor_sync(0xffffffffu, s2, 1);
        s2 += __shfl_xor_sync(0xffffffffu, s2, 2);
        float rinv = 1.f / fmaxf(sqrtf(s2), 1e-12f);
        #pragma unroll
        for (int oq = 0; oq < 32; oq++)
            tf[px*128 + q*32 + oq] = acc[oq] * rinv;
    }
    __syncthreads();

    const int i  = t >> 2;
    const int j0 = (t & 3) << 4;
    {
        float acc[16];
        #pragma unroll
        for (int j = 0; j < 16; j++) acc[j] = 0.f;
        const float4* fi = reinterpret_cast<const float4*>(tf + i*128);
        #pragma unroll 4
        for (int k4 = 0; k4 < 32; k4++) {
            float4 a = fi[k4];
            #pragma unroll
            for (int j = 0; j < 16; j++) {
                float4 c = reinterpret_cast<const float4*>(tf + (j0 + j)*128)[k4];
                acc[j] += a.x*c.x + a.y*c.y + a.z*c.z + a.w*c.w;
            }
        }
        float dpart = 0.f;
        #pragma unroll
        for (int j = 0; j < 16; j++) {
            float s = acc[j] * 10.f;
            simM[i*65 + j0 + j] = s;
            dpart += expf(s);
        }
        dpart += __shfl_xor_sync(0xffffffffu, dpart, 1);
        dpart += __shfl_xor_sync(0xffffffffu, dpart, 2);
        if ((t & 3) == 0) denom[i] = dpart;
    }
    __syncthreads();

    {
        float lacc = 0.f;
        float di  = denom[i];
        float twi = tw[i];
        #pragma unroll
        for (int j = 0; j < 16; j++) {
            int jj = j0 + j;
            float s = simM[i*65 + jj];
            if (s > 0.7f && jj != i) {
                float lp = logf(expf(s)/di + 1e-10f);
                lacc += twi * tw[jj] * lp;
            }
        }
        red[t] = lacc;
    }
    __syncthreads();
    for (int sft = 128; sft > 0; sft >>= 1) { if (t < sft) red[t] += red[t+sft]; __syncthreads(); }
    if (t == 0) {
        float tsum = 0.f;
        for (int j = 0; j < 64; j++) tsum += tw[j];
        g_loss[b] = -(0.1f/0.07f) * red[0] / tsum;
    }
}

// ---------------- final mean * LOSS_WEIGHT ----------------
__global__ void k_final(float* out) {
    int t = threadIdx.x;
    float v = (t < 16) ? g_loss[t] : 0.f;
    #pragma unroll
    for (int o = 16; o > 0; o >>= 1) v += __shfl_down_sync(0xffffffffu, v, o);
    if (t == 0) out[0] = (v / 16.0f) * 0.1f;
}

// ---------------- launch ----------------
extern "C" void kernel_launch(void* const* d_in, const int* in_sizes, int n_in,
                              void* d_out, int out_size) {
    const float* feats = (const float*)d_in[0];
    const int*   labels= (const int*)d_in[1];
    const float* W1   = (const float*)d_in[2];
    const float* b1   = (const float*)d_in[3];
    const float* gamma= (const float*)d_in[4];
    const float* beta = (const float*)d_in[5];
    const float* W2   = (const float*)d_in[6];
    const float* b2   = (const float*)d_in[7];
    const float* Wa1  = (const float*)d_in[8];
    const float* ba1  = (const float*)d_in[9];
    const float* Wa2  = (const float*)d_in[10];
    const float* ba2  = (const float*)d_in[11];

    cudaFuncSetAttribute(k_fused, cudaFuncAttributeMaxDynamicSharedMemorySize, DYNB);
    cudaFuncSetAttribute(k_projloss, cudaFuncAttributeMaxDynamicSharedMemorySize, PL_DYNB);

    k_fused<<<NCONVB + NSAMPB, 256, DYNB>>>(feats, W1, Wa1, labels);
    k_projloss<<<16, 256, PL_DYNB>>>(b1, gamma, beta, W2, b2, ba1, Wa2, ba2);
    k_final<<<1, 32>>>((float*)d_out);
}

// round 7
// speedup vs baseline: 2.3663x; 1.3834x over previous
#include <cuda_runtime.h>
#include <cuda_fp16.h>
#include <mma.h>
#include <cstdint>

using namespace nvcuda;

#define CC 2048
#define HWN 4096
#define NCONVB 512
#define NSAMPB 128   // 16 img x 8 K-splits

// ---------------- device scratch ----------------
__device__ __half g_W1h[128*2048];
__device__ float g_p1[128*512];      // [ch][block] transposed partials
__device__ float g_p2[128*512];
__device__ float g_mean[128];
__device__ float g_istd[128];
__device__ float g_hs8[8*1024*192];
__device__ float g_tf[1024*128];
__device__ float g_tw[1024];
__device__ float g_loss[16];

// ---------------- helpers ----------------
__device__ __forceinline__ void cpasync16(void* s, const void* g) {
    unsigned sa = (unsigned)__cvta_generic_to_shared(s);
    asm volatile("cp.async.cg.shared.global [%0], [%1], 16;\n" :: "r"(sa), "l"(g));
}
__device__ __forceinline__ void cpcommit() { asm volatile("cp.async.commit_group;\n"); }
template<int N> __device__ __forceinline__ void cpwait() {
    asm volatile("cp.async.wait_group %0;\n" :: "n"(N));
}
__device__ __forceinline__ uint32_t h2u(float x, float y) {
    __half2 h = __floats2half2_rn(x, y);
    return *reinterpret_cast<uint32_t*>(&h);
}

// ---------------- W1 -> half pre-convert ----------------
__global__ void k_prep(const float* __restrict__ W1) {
    int idx = blockIdx.x*256 + threadIdx.x;     // 65536 float4
    float4 v = reinterpret_cast<const float4*>(W1)[idx];
    uint2 u; u.x = h2u(v.x, v.y); u.y = h2u(v.z, v.w);
    *reinterpret_cast<uint2*>(g_W1h + idx*4) = u;
}

// smem: A f32 ring 3x16896 | A f16 2x8704 | W f16 4x10240  = 109056 B
#define DYNB 109056

__global__ __launch_bounds__(256, 2)
void k_fused(const float* __restrict__ feats, const float* __restrict__ W1,
             const float* __restrict__ Wa1,  const int* __restrict__ labels) {
    extern __shared__ char dynC[];
    float* dyn = (float*)dynC;
    __shared__ float r1[256], r2[256];
    const int tid = threadIdx.x;

    if (blockIdx.x >= NCONVB) {
        // ============ sampled path: exact fp32 conv at 64 label==1 pixels ============
        const int sb = blockIdx.x - NCONVB;
        const int z = sb & 7;
        const int b = sb >> 3;
        float* Fs  = dyn;                    // [64][33]
        float* Ws2 = dyn + 64*33;            // [192][33]
        int*   pix = (int*)(dyn + 64*33 + 192*33);

        if (tid < 64) pix[tid] = 0;
        __syncthreads();
        if (tid < 32) {
            const int lane = tid;
            int probe = 0;
            #pragma unroll
            for (int i = lane; i < 64; i += 32) probe |= labels[2*(i*512)+1];
            unsigned any = __ballot_sync(0xffffffffu, probe != 0);
            const bool is64 = (any == 0u);
            const long long* L64 = (const long long*)labels;
            int base = 0;
            for (int c = 0; c < 128; c++) {
                if (base >= 64) break;
                int p = (c << 5) + lane;
                long long v = is64 ? L64[(size_t)b*HWN + p]
                                   : (long long)labels[(size_t)b*HWN + p];
                bool valid = (v == 1);
                unsigned m = __ballot_sync(0xffffffffu, valid);
                int pre = __popc(m & ((1u << lane) - 1u));
                if (valid && base + pre < 64) pix[base + pre] = p;
                base += __popc(m);
            }
        }
        __syncthreads();

        float acc[4][12];
        #pragma unroll
        for (int i = 0; i < 4; i++)
            #pragma unroll
            for (int j = 0; j < 12; j++) acc[i][j] = 0.f;

        const int pg = tid & 15;
        const int cg = tid >> 4;
        const size_t fb = (size_t)b*CC*HWN;
        const int kbase = z * 256;

        for (int chn = 0; chn < 8; chn++) {
            int k0 = kbase + chn*32;
            __syncthreads();
            #pragma unroll
            for (int i = 0; i < 8; i++) {
                int idx = tid + i*256;
                int px = idx >> 5, kk = idx & 31;
                Fs[px*33 + kk] = feats[fb + (size_t)(k0+kk)*HWN + pix[px]];
            }
            #pragma unroll
            for (int i = 0; i < 24; i++) {
                int idx = tid + i*256;
                int r = idx >> 5, kk = idx & 31;
                Ws2[r*33 + kk] = (r < 128) ? W1[r*CC + k0 + kk]
                                           : Wa1[(r-128)*CC + k0 + kk];
            }
            __syncthreads();
            #pragma unroll 4
            for (int kk = 0; kk < 32; kk++) {
                float fv[4];
                #pragma unroll
                for (int i = 0; i < 4; i++) fv[i] = Fs[(pg*4 + i)*33 + kk];
                #pragma unroll
                for (int j = 0; j < 12; j++) {
                    float w = Ws2[(cg*12 + j)*33 + kk];
                    #pragma unroll
                    for (int i = 0; i < 4; i++) acc[i][j] += fv[i]*w;
                }
            }
        }
        #pragma unroll
        for (int i = 0; i < 4; i++)
            #pragma unroll
            for (int j = 0; j < 12; j++)
                g_hs8[(size_t)z*196608 + (b*64 + pg*4 + i)*192 + cg*12 + j] = acc[i][j];
        return;
    }

    // ============ conv1 stats: f16 wmma, M=128 x N=128, overlapped convert ===========
    const int cb = blockIdx.x;
    const int b  = cb >> 5;
    const int p0 = (cb & 31) * 128;
    const float* F = feats + (size_t)b*CC*HWN + p0;

    const int wid = tid >> 5;
    const int wr  = wid & 3;    // 32-pixel group
    const int wc  = wid >> 2;   // 64-channel group

    wmma::fragment<wmma::accumulator,16,16,16,half> acc[2][4];
    #pragma unroll
    for (int i = 0; i < 2; i++)
        #pragma unroll
        for (int j = 0; j < 4; j++) wmma::fill_fragment(acc[i][j], __float2half(0.f));

    auto Af = [&](int s) { return dyn + s*4224; };                       // [32k][132] f32
    auto Ah = [&](int s) { return (half*)(dynC + 50688 + s*8704); };     // [32k][136]
    auto Wh = [&](int s) { return (half*)(dynC + 68096 + s*10240); };    // [128ch][40]

    auto issue = [&](int kc) {
        float* A = Af(kc % 3);
        half*  W = Wh(kc & 3);
        const float* Fg = F + (size_t)(kc*32)*HWN;
        #pragma unroll
        for (int i = 0; i < 4; i++) {
            int idx = tid + i*256;
            int k = idx >> 5, px4 = (idx & 31) << 2;
            cpasync16(A + k*132 + px4, Fg + (size_t)k*HWN + px4);
        }
        const __half* Wg = g_W1h + kc*32;
        #pragma unroll
        for (int i = 0; i < 2; i++) {
            int idx = tid + i*256;
            int ch = idx >> 2, k8 = (idx & 3) << 3;
            cpasync16(W + ch*40 + k8, Wg + ch*2048 + k8);
        }
        cpcommit();
    };
    auto convert = [&](int kc) {
        float* A = Af(kc % 3);
        half* Ab = Ah(kc & 1);
        #pragma unroll
        for (int i = 0; i < 4; i++) {
            int idx = tid + i*256;
            int k = idx >> 5, px4 = (idx & 31) << 2;
            float4 v = *reinterpret_cast<float4*>(A + k*132 + px4);
            uint2 u; u.x = h2u(v.x, v.y); u.y = h2u(v.z, v.w);
            *reinterpret_cast<uint2*>(Ab + k*136 + px4) = u;
        }
    };
    auto compute = [&](int kc) {
        const half* Ab = Ah(kc & 1);
        const half* Wb = Wh(kc & 3);
        #pragma unroll
        for (int ks = 0; ks < 32; ks += 16) {
            wmma::fragment<wmma::matrix_a,16,16,16,half,wmma::col_major> af[2];
            #pragma unroll
            for (int i = 0; i < 2; i++)
                wmma::load_matrix_sync(af[i], Ab + ks*136 + wr*32 + i*16, 136);
            wmma::fragment<wmma::matrix_b,16,16,16,half,wmma::col_major> bf[4];
            #pragma unroll
            for (int j = 0; j < 4; j++)
                wmma::load_matrix_sync(bf[j], Wb + (wc*64 + j*16)*40 + ks, 40);
            #pragma unroll
            for (int i = 0; i < 2; i++)
                #pragma unroll
                for (int j = 0; j < 4; j++)
                    wmma::mma_sync(acc[i][j], af[i], bf[j], acc[i][j]);
        }
    };

    issue(0); issue(1);
    cpwait<1>();
    __syncthreads();
    convert(0);

    for (int kc = 0; kc < 64; kc++) {
        if (kc + 2 < 64) { issue(kc + 2); cpwait<1>(); }
        else             { cpwait<0>(); }
        __syncthreads();
        if (kc + 1 < 64) convert(kc + 1);
        compute(kc);
    }
    __syncthreads();

    // Epilogue: f16 acc -> smem -> per-channel sum/sumsq, transposed partials
    half* Cs16 = (half*)dynC;   // [128 px][136]
    #pragma unroll
    for (int i = 0; i < 2; i++)
        #pragma unroll
        for (int j = 0; j < 4; j++)
            wmma::store_matrix_sync(Cs16 + (wr*32 + i*16)*136 + wc*64 + j*16,
                                    acc[i][j], 136, wmma::mem_row_major);
    __syncthreads();
    {
        const int ch = tid & 127;
        const int sg = tid >> 7;
        float s = 0.f, s2 = 0.f;
        #pragma unroll 4
        for (int p = sg*64; p < sg*64 + 64; p++) {
            float v = __half2float(Cs16[p*136 + ch]);
            s += v; s2 += v*v;
        }
        r1[tid] = s; r2[tid] = s2;
        __syncthreads();
        if (tid < 128) {
            g_p1[tid*512 + cb] = r1[tid] + r1[tid+128];
            g_p2[tid*512 + cb] = r2[tid] + r2[tid+128];
        }
    }
}

// ---------------- stats: reduce per-block partials (grid 128 = one ch each) ----------
__global__ void k_stats() {
    __shared__ float sS[256], sS2[256];
    const int ch = blockIdx.x;
    const int t = threadIdx.x;
    if (ch == 0 && t < 16) g_loss[t] = 0.f;
    float S  = g_p1[ch*512 + t] + g_p1[ch*512 + t + 256];
    float S2 = g_p2[ch*512 + t] + g_p2[ch*512 + t + 256];
    sS[t] = S; sS2[t] = S2;
    __syncthreads();
    for (int s = 128; s > 0; s >>= 1) {
        if (t < s) { sS[t] += sS[t+s]; sS2[t] += sS2[t+s]; }
        __syncthreads();
    }
    if (t == 0) {
        float m   = sS[0] * (1.f/65536.f);
        float var = sS2[0] * (1.f/65536.f) - m*m;
        g_mean[ch] = m;
        g_istd[ch] = rsqrtf(var + 1e-5f);
    }
}

// ---------------- per-pixel: BN + conv2 + normalize + attention (grid 1024) ----------
__global__ void k_proj(const float* __restrict__ b1, const float* __restrict__ gamma,
                       const float* __restrict__ beta, const float* __restrict__ W2,
                       const float* __restrict__ b2,  const float* __restrict__ ba1,
                       const float* __restrict__ Wa2, const float* __restrict__ ba2) {
    __shared__ float xr[128];
    __shared__ float ar[64];
    __shared__ float red[128];
    const int t = threadIdx.x;
    const int pid = blockIdx.x;
    {
        float h = b1[t];
        #pragma unroll
        for (int z = 0; z < 8; z++) h += g_hs8[(size_t)z*196608 + pid*192 + t];
        float xn = (h - (g_mean[t] + b1[t])) * g_istd[t] * gamma[t] + beta[t];
        xr[t] = fmaxf(xn, 0.f);
    }
    if (t < 64) {
        float ha = 0.f;
        #pragma unroll
        for (int z = 0; z < 8; z++) ha += g_hs8[(size_t)z*196608 + pid*192 + 128 + t];
        ar[t] = fmaxf(ha + ba1[t], 0.f);
    }
    __syncthreads();

    float acc = b2[t];
    #pragma unroll 8
    for (int k = 0; k < 128; k++) acc += W2[t*128 + k] * xr[k];

    red[t] = acc*acc;
    __syncthreads();
    for (int s = 64; s > 0; s >>= 1) { if (t < s) red[t] += red[t+s]; __syncthreads(); }
    float rinv = 1.f / fmaxf(sqrtf(red[0]), 1e-12f);
    g_tf[pid*128 + t] = acc * rinv;

    if (t < 32) {
        float z = Wa2[t]*ar[t] + Wa2[t+32]*ar[t+32];
        #pragma unroll
        for (int o = 16; o > 0; o >>= 1) z += __shfl_down_sync(0xffffffffu, z, o);
        if (t == 0) g_tw[pid] = 1.f / (1.f + expf(-(z + ba2[0])));
    }
}

// ---------------- contrastive loss (grid 64 = 4 row-blocks per image) ----------------
__global__ __launch_bounds__(256) void k_loss() {
    __shared__ float tf[64*128];
    __shared__ float tw[64];
    __shared__ float red[256];
    const int t = threadIdx.x;
    const int b  = blockIdx.x >> 2;
    const int rg = blockIdx.x & 3;

    #pragma unroll
    for (int i = 0; i < 8; i++)
        reinterpret_cast<float4*>(tf)[t + i*256] =
            reinterpret_cast<const float4*>(g_tf + b*8192)[t + i*256];
    if (t < 64) tw[t] = g_tw[b*64 + t];
    __syncthreads();

    const int lr = t >> 4;            // 16 local rows
    const int cg = t & 15;            // 16 col groups of 4
    const int i  = rg*16 + lr;

    float s[4];
    {
        float a0 = 0.f, a1 = 0.f, a2 = 0.f, a3 = 0.f;
        const float4* fi = reinterpret_cast<const float4*>(tf + i*128);
        const float4* c0 = reinterpret_cast<const float4*>(tf + (cg*4+0)*128);
        const float4* c1 = reinterpret_cast<const float4*>(tf + (cg*4+1)*128);
        const float4* c2 = reinterpret_cast<const float4*>(tf + (cg*4+2)*128);
        const float4* c3 = reinterpret_cast<const float4*>(tf + (cg*4+3)*128);
        #pragma unroll 8
        for (int k4 = 0; k4 < 32; k4++) {
            float4 a = fi[k4];
            float4 v0 = c0[k4], v1 = c1[k4], v2 = c2[k4], v3 = c3[k4];
            a0 += a.x*v0.x + a.y*v0.y + a.z*v0.z + a.w*v0.w;
            a1 += a.x*v1.x + a.y*v1.y + a.z*v1.z + a.w*v1.w;
            a2 += a.x*v2.x + a.y*v2.y + a.z*v2.z + a.w*v2.w;
            a3 += a.x*v3.x + a.y*v3.y + a.z*v3.z + a.w*v3.w;
        }
        s[0] = a0*10.f; s[1] = a1*10.f; s[2] = a2*10.f; s[3] = a3*10.f;
    }
    // row denominator across the 16 lanes of this row
    float d = expf(s[0]) + expf(s[1]) + expf(s[2]) + expf(s[3]);
    d += __shfl_xor_sync(0xffffffffu, d, 1);
    d += __shfl_xor_sync(0xffffffffu, d, 2);
    d += __shfl_xor_sync(0xffffffffu, d, 4);
    d += __shfl_xor_sync(0xffffffffu, d, 8);

    float lacc = 0.f;
    float twi = tw[i];
    #pragma unroll
    for (int j = 0; j < 4; j++) {
        int jj = cg*4 + j;
        if (s[j] > 0.7f && jj != i)
            lacc += twi * tw[jj] * logf(expf(s[j])/d + 1e-10f);
    }
    red[t] = lacc;
    __syncthreads();
    for (int sft = 128; sft > 0; sft >>= 1) { if (t < sft) red[t] += red[t+sft]; __syncthreads(); }
    if (t == 0) atomicAdd(&g_loss[b], red[0]);
}

// ---------------- final: per-image normalize + mean * LOSS_WEIGHT ----------------
__global__ void k_final(float* out) {
    int t = threadIdx.x;
    float v = 0.f;
    if (t < 16) {
        float tsum = 0.f;
        for (int j = 0; j < 64; j++) tsum += g_tw[t*64 + j];
        v = -(0.1f/0.07f) * g_loss[t] / tsum;
    }
    #pragma unroll
    for (int o = 16; o > 0; o >>= 1) v += __shfl_down_sync(0xffffffffu, v, o);
    if (t == 0) out[0] = (v / 16.0f) * 0.1f;
}

// ---------------- launch ----------------
extern "C" void kernel_launch(void* const* d_in, const int* in_sizes, int n_in,
                              void* d_out, int out_size) {
    const float* feats = (const float*)d_in[0];
    const int*   labels= (const int*)d_in[1];
    const float* W1   = (const float*)d_in[2];
    const float* b1   = (const float*)d_in[3];
    const float* gamma= (const float*)d_in[4];
    const float* beta = (const float*)d_in[5];
    const float* W2   = (const float*)d_in[6];
    const float* b2   = (const float*)d_in[7];
    const float* Wa1  = (const float*)d_in[8];
    const float* ba1  = (const float*)d_in[9];
    const float* Wa2  = (const float*)d_in[10];
    const float* ba2  = (const float*)d_in[11];

    cudaFuncSetAttribute(k_fused, cudaFuncAttributeMaxDynamicSharedMemorySize, DYNB);

    k_prep<<<256, 256>>>(W1);
    k_fused<<<NCONVB + NSAMPB, 256, DYNB>>>(feats, W1, Wa1, labels);
    k_stats<<<128, 256>>>();
    k_proj<<<1024, 128>>>(b1, gamma, beta, W2, b2, ba1, Wa2, ba2);
    k_loss<<<64, 256>>>();
    k_final<<<1, 32>>>((float*)d_out);
}

// round 8
// speedup vs baseline: 2.8252x; 1.1939x over previous
#include <cuda_runtime.h>
#include <cuda_fp16.h>
#include <mma.h>
#include <cstdint>

using namespace nvcuda;

#define CC 2048
#define HWN 4096
#define NCONVB 512
#define NSAMPB 128   // 16 img x 8 K-splits

// ---------------- device scratch ----------------
__device__ __half g_W1h[128*2048];
__device__ float g_W2t[128*128];     // transposed W2: [k][o]
__device__ float g_p1[128*512];      // [ch][block] transposed partials
__device__ float g_p2[128*512];
__device__ float g_mean[128];
__device__ float g_istd[128];
__device__ float g_hs8[8*1024*192];
__device__ float g_tf[1024*128];
__device__ float g_tw[1024];
__device__ float g_loss[16];

// ---------------- helpers ----------------
__device__ __forceinline__ void cpasync16(void* s, const void* g) {
    unsigned sa = (unsigned)__cvta_generic_to_shared(s);
    asm volatile("cp.async.cg.shared.global [%0], [%1], 16;\n" :: "r"(sa), "l"(g));
}
__device__ __forceinline__ void cpcommit() { asm volatile("cp.async.commit_group;\n"); }
template<int N> __device__ __forceinline__ void cpwait() {
    asm volatile("cp.async.wait_group %0;\n" :: "n"(N));
}
__device__ __forceinline__ uint32_t h2u(float x, float y) {
    __half2 h = __floats2half2_rn(x, y);
    return *reinterpret_cast<uint32_t*>(&h);
}

// ---------------- prep: W1 -> half, W2 -> transposed ----------------
__global__ void k_prep(const float* __restrict__ W1, const float* __restrict__ W2) {
    if (blockIdx.x < 256) {
        int idx = blockIdx.x*256 + threadIdx.x;     // 65536 float4
        float4 v = reinterpret_cast<const float4*>(W1)[idx];
        uint2 u; u.x = h2u(v.x, v.y); u.y = h2u(v.z, v.w);
        *reinterpret_cast<uint2*>(g_W1h + idx*4) = u;
    } else {
        int idx = (blockIdx.x - 256)*256 + threadIdx.x;  // 16384 floats
        int o = idx >> 7, k = idx & 127;
        g_W2t[k*128 + o] = W2[idx];
    }
}

// smem: A f32 ring 3x16896 | A f16 2x8704 | W f16 4x10240  = 109056 B
#define DYNB 109056

__global__ __launch_bounds__(256, 2)
void k_fused(const float* __restrict__ feats, const float* __restrict__ W1,
             const float* __restrict__ Wa1,  const int* __restrict__ labels) {
    extern __shared__ char dynC[];
    float* dyn = (float*)dynC;
    __shared__ float r1[256], r2[256];
    const int tid = threadIdx.x;

    if (blockIdx.x >= NCONVB) {
        // ============ sampled path: exact fp32 conv at 64 label==1 pixels ============
        const int sb = blockIdx.x - NCONVB;
        const int z = sb & 7;
        const int b = sb >> 3;
        float* Fs  = dyn;                    // [64][33]
        float* Ws2 = dyn + 64*33;            // [192][33]
        int*   pix = (int*)(dyn + 64*33 + 192*33);

        if (tid < 64) pix[tid] = 0;
        __syncthreads();
        if (tid < 32) {
            const int lane = tid;
            int probe = 0;
            #pragma unroll
            for (int i = lane; i < 64; i += 32) probe |= labels[2*(i*512)+1];
            unsigned any = __ballot_sync(0xffffffffu, probe != 0);
            const bool is64 = (any == 0u);
            const long long* L64 = (const long long*)labels;
            int base = 0;
            for (int c = 0; c < 128; c++) {
                if (base >= 64) break;
                int p = (c << 5) + lane;
                long long v = is64 ? L64[(size_t)b*HWN + p]
                                   : (long long)labels[(size_t)b*HWN + p];
                bool valid = (v == 1);
                unsigned m = __ballot_sync(0xffffffffu, valid);
                int pre = __popc(m & ((1u << lane) - 1u));
                if (valid && base + pre < 64) pix[base + pre] = p;
                base += __popc(m);
            }
        }
        __syncthreads();

        float acc[4][12];
        #pragma unroll
        for (int i = 0; i < 4; i++)
            #pragma unroll
            for (int j = 0; j < 12; j++) acc[i][j] = 0.f;

        const int pg = tid & 15;
        const int cg = tid >> 4;
        const size_t fb = (size_t)b*CC*HWN;
        const int kbase = z * 256;

        for (int chn = 0; chn < 8; chn++) {
            int k0 = kbase + chn*32;
            __syncthreads();
            #pragma unroll
            for (int i = 0; i < 8; i++) {
                int idx = tid + i*256;
                int px = idx >> 5, kk = idx & 31;
                Fs[px*33 + kk] = feats[fb + (size_t)(k0+kk)*HWN + pix[px]];
            }
            #pragma unroll
            for (int i = 0; i < 24; i++) {
                int idx = tid + i*256;
                int r = idx >> 5, kk = idx & 31;
                Ws2[r*33 + kk] = (r < 128) ? W1[r*CC + k0 + kk]
                                           : Wa1[(r-128)*CC + k0 + kk];
            }
            __syncthreads();
            #pragma unroll 4
            for (int kk = 0; kk < 32; kk++) {
                float fv[4];
                #pragma unroll
                for (int i = 0; i < 4; i++) fv[i] = Fs[(pg*4 + i)*33 + kk];
                #pragma unroll
                for (int j = 0; j < 12; j++) {
                    float w = Ws2[(cg*12 + j)*33 + kk];
                    #pragma unroll
                    for (int i = 0; i < 4; i++) acc[i][j] += fv[i]*w;
                }
            }
        }
        #pragma unroll
        for (int i = 0; i < 4; i++)
            #pragma unroll
            for (int j = 0; j < 12; j++)
                g_hs8[(size_t)z*196608 + (b*64 + pg*4 + i)*192 + cg*12 + j] = acc[i][j];
        return;
    }

    // ============ conv1 stats: f16 wmma, M=128 x N=128, compute-first overlap ========
    const int cb = blockIdx.x;
    const int b  = cb >> 5;
    const int p0 = (cb & 31) * 128;
    const float* F = feats + (size_t)b*CC*HWN + p0;

    const int wid = tid >> 5;
    const int wr  = wid & 3;    // 32-pixel group
    const int wc  = wid >> 2;   // 64-channel group

    wmma::fragment<wmma::accumulator,16,16,16,half> acc[2][4];
    #pragma unroll
    for (int i = 0; i < 2; i++)
        #pragma unroll
        for (int j = 0; j < 4; j++) wmma::fill_fragment(acc[i][j], __float2half(0.f));

    auto Af = [&](int s) { return dyn + s*4224; };                       // [32k][132] f32
    auto Ah = [&](int s) { return (half*)(dynC + 50688 + s*8704); };     // [32k][136]
    auto Wh = [&](int s) { return (half*)(dynC + 68096 + s*10240); };    // [128ch][40]

    auto issue = [&](int kc) {
        float* A = Af(kc % 3);
        half*  W = Wh(kc & 3);
        const float* Fg = F + (size_t)(kc*32)*HWN;
        #pragma unroll
        for (int i = 0; i < 4; i++) {
            int idx = tid + i*256;
            int k = idx >> 5, px4 = (idx & 31) << 2;
            cpasync16(A + k*132 + px4, Fg + (size_t)k*HWN + px4);
        }
        const __half* Wg = g_W1h + kc*32;
        #pragma unroll
        for (int i = 0; i < 2; i++) {
            int idx = tid + i*256;
            int ch = idx >> 2, k8 = (idx & 3) << 3;
            cpasync16(W + ch*40 + k8, Wg + ch*2048 + k8);
        }
        cpcommit();
    };
    auto convert = [&](int kc) {
        float* A = Af(kc % 3);
        half* Ab = Ah(kc & 1);
        #pragma unroll
        for (int i = 0; i < 4; i++) {
            int idx = tid + i*256;
            int k = idx >> 5, px4 = (idx & 31) << 2;
            float4 v = *reinterpret_cast<float4*>(A + k*132 + px4);
            uint2 u; u.x = h2u(v.x, v.y); u.y = h2u(v.z, v.w);
            *reinterpret_cast<uint2*>(Ab + k*136 + px4) = u;
        }
    };
    auto compute = [&](int kc) {
        const half* Ab = Ah(kc & 1);
        const half* Wb = Wh(kc & 3);
        #pragma unroll
        for (int ks = 0; ks < 32; ks += 16) {
            wmma::fragment<wmma::matrix_a,16,16,16,half,wmma::col_major> af[2];
            #pragma unroll
            for (int i = 0; i < 2; i++)
                wmma::load_matrix_sync(af[i], Ab + ks*136 + wr*32 + i*16, 136);
            wmma::fragment<wmma::matrix_b,16,16,16,half,wmma::col_major> bf[4];
            #pragma unroll
            for (int j = 0; j < 4; j++)
                wmma::load_matrix_sync(bf[j], Wb + (wc*64 + j*16)*40 + ks, 40);
            #pragma unroll
            for (int i = 0; i < 2; i++)
                #pragma unroll
                for (int j = 0; j < 4; j++)
                    wmma::mma_sync(acc[i][j], af[i], bf[j], acc[i][j]);
        }
    };

    issue(0); issue(1);
    cpwait<1>();
    __syncthreads();
    convert(0);

    for (int kc = 0; kc < 64; kc++) {
        if (kc + 2 < 64) { issue(kc + 2); cpwait<1>(); }
        else             { cpwait<0>(); }
        __syncthreads();
        // compute first: HMMAs queue immediately; convert (needed only next
        // chunk, disjoint buffers) fills the tensor-pipe shadow.
        compute(kc);
        if (kc + 1 < 64) convert(kc + 1);
    }
    __syncthreads();

    // Epilogue: f16 acc -> smem -> per-channel sum/sumsq, transposed partials
    half* Cs16 = (half*)dynC;   // [128 px][136]
    #pragma unroll
    for (int i = 0; i < 2; i++)
        #pragma unroll
        for (int j = 0; j < 4; j++)
            wmma::store_matrix_sync(Cs16 + (wr*32 + i*16)*136 + wc*64 + j*16,
                                    acc[i][j], 136, wmma::mem_row_major);
    __syncthreads();
    {
        const int ch = tid & 127;
        const int sg = tid >> 7;
        float s = 0.f, s2 = 0.f;
        #pragma unroll 4
        for (int p = sg*64; p < sg*64 + 64; p++) {
            float v = __half2float(Cs16[p*136 + ch]);
            s += v; s2 += v*v;
        }
        r1[tid] = s; r2[tid] = s2;
        __syncthreads();
        if (tid < 128) {
            g_p1[tid*512 + cb] = r1[tid] + r1[tid+128];
            g_p2[tid*512 + cb] = r2[tid] + r2[tid+128];
        }
    }
}

// ---------------- stats: reduce per-block partials (grid 128 = one ch each) ----------
__global__ void k_stats() {
    __shared__ float sS[256], sS2[256];
    const int ch = blockIdx.x;
    const int t = threadIdx.x;
    if (ch == 0 && t < 16) g_loss[t] = 0.f;
    float S  = g_p1[ch*512 + t] + g_p1[ch*512 + t + 256];
    float S2 = g_p2[ch*512 + t] + g_p2[ch*512 + t + 256];
    sS[t] = S; sS2[t] = S2;
    __syncthreads();
    for (int s = 128; s > 0; s >>= 1) {
        if (t < s) { sS[t] += sS[t+s]; sS2[t] += sS2[t+s]; }
        __syncthreads();
    }
    if (t == 0) {
        float m   = sS[0] * (1.f/65536.f);
        float var = sS2[0] * (1.f/65536.f) - m*m;
        g_mean[ch] = m;
        g_istd[ch] = rsqrtf(var + 1e-5f);
    }
}

// ---------------- per-pixel: BN + conv2 (coalesced W2t) + normalize + attention -------
__global__ void k_proj(const float* __restrict__ b1, const float* __restrict__ gamma,
                       const float* __restrict__ beta, const float* __restrict__ b2,
                       const float* __restrict__ ba1, const float* __restrict__ Wa2,
                       const float* __restrict__ ba2) {
    __shared__ float xr[128];
    __shared__ float ar[64];
    __shared__ float red[128];
    const int t = threadIdx.x;
    const int pid = blockIdx.x;
    {
        float h = b1[t];
        #pragma unroll
        for (int z = 0; z < 8; z++) h += g_hs8[(size_t)z*196608 + pid*192 + t];
        float xn = (h - (g_mean[t] + b1[t])) * g_istd[t] * gamma[t] + beta[t];
        xr[t] = fmaxf(xn, 0.f);
    }
    if (t < 64) {
        float ha = 0.f;
        #pragma unroll
        for (int z = 0; z < 8; z++) ha += g_hs8[(size_t)z*196608 + pid*192 + 128 + t];
        ar[t] = fmaxf(ha + ba1[t], 0.f);
    }
    __syncthreads();

    float acc = b2[t];
    #pragma unroll 8
    for (int k = 0; k < 128; k++) acc += g_W2t[k*128 + t] * xr[k];   // coalesced

    red[t] = acc*acc;
    __syncthreads();
    for (int s = 64; s > 0; s >>= 1) { if (t < s) red[t] += red[t+s]; __syncthreads(); }
    float rinv = 1.f / fmaxf(sqrtf(red[0]), 1e-12f);
    g_tf[pid*128 + t] = acc * rinv;

    if (t < 32) {
        float z = Wa2[t]*ar[t] + Wa2[t+32]*ar[t+32];
        #pragma unroll
        for (int o = 16; o > 0; o >>= 1) z += __shfl_down_sync(0xffffffffu, z, o);
        if (t == 0) g_tw[pid] = 1.f / (1.f + expf(-(z + ba2[0])));
    }
}

// ---------------- contrastive loss (grid 64 = 4 row-blocks per image) ----------------
__global__ __launch_bounds__(256) void k_loss() {
    __shared__ float tf[64*128];
    __shared__ float tw[64];
    __shared__ float red[256];
    const int t = threadIdx.x;
    const int b  = blockIdx.x >> 2;
    const int rg = blockIdx.x & 3;

    #pragma unroll
    for (int i = 0; i < 8; i++)
        reinterpret_cast<float4*>(tf)[t + i*256] =
            reinterpret_cast<const float4*>(g_tf + b*8192)[t + i*256];
    if (t < 64) tw[t] = g_tw[b*64 + t];
    __syncthreads();

    const int lr = t >> 4;
    const int cg = t & 15;
    const int i  = rg*16 + lr;

    float s[4];
    {
        float a0 = 0.f, a1 = 0.f, a2 = 0.f, a3 = 0.f;
        const float4* fi = reinterpret_cast<const float4*>(tf + i*128);
        const float4* c0 = reinterpret_cast<const float4*>(tf + (cg*4+0)*128);
        const float4* c1 = reinterpret_cast<const float4*>(tf + (cg*4+1)*128);
        const float4* c2 = reinterpret_cast<const float4*>(tf + (cg*4+2)*128);
        const float4* c3 = reinterpret_cast<const float4*>(tf + (cg*4+3)*128);
        #pragma unroll 8
        for (int k4 = 0; k4 < 32; k4++) {
            float4 a = fi[k4];
            float4 v0 = c0[k4], v1 = c1[k4], v2 = c2[k4], v3 = c3[k4];
            a0 += a.x*v0.x + a.y*v0.y + a.z*v0.z + a.w*v0.w;
            a1 += a.x*v1.x + a.y*v1.y + a.z*v1.z + a.w*v1.w;
            a2 += a.x*v2.x + a.y*v2.y + a.z*v2.z + a.w*v2.w;
            a3 += a.x*v3.x + a.y*v3.y + a.z*v3.z + a.w*v3.w;
        }
        s[0] = a0*10.f; s[1] = a1*10.f; s[2] = a2*10.f; s[3] = a3*10.f;
    }
    float d = expf(s[0]) + expf(s[1]) + expf(s[2]) + expf(s[3]);
    d += __shfl_xor_sync(0xffffffffu, d, 1);
    d += __shfl_xor_sync(0xffffffffu, d, 2);
    d += __shfl_xor_sync(0xffffffffu, d, 4);
    d += __shfl_xor_sync(0xffffffffu, d, 8);

    float lacc = 0.f;
    float twi = tw[i];
    #pragma unroll
    for (int j = 0; j < 4; j++) {
        int jj = cg*4 + j;
        if (s[j] > 0.7f && jj != i)
            lacc += twi * tw[jj] * logf(expf(s[j])/d + 1e-10f);
    }
    red[t] = lacc;
    __syncthreads();
    for (int sft = 128; sft > 0; sft >>= 1) { if (t < sft) red[t] += red[t+sft]; __syncthreads(); }
    if (t == 0) atomicAdd(&g_loss[b], red[0]);
}

// ---------------- final: per-image normalize + mean * LOSS_WEIGHT ----------------
__global__ void k_final(float* out) {
    int t = threadIdx.x;
    float v = 0.f;
    if (t < 16) {
        float tsum = 0.f;
        for (int j = 0; j < 64; j++) tsum += g_tw[t*64 + j];
        v = -(0.1f/0.07f) * g_loss[t] / tsum;
    }
    #pragma unroll
    for (int o = 16; o > 0; o >>= 1) v += __shfl_down_sync(0xffffffffu, v, o);
    if (t == 0) out[0] = (v / 16.0f) * 0.1f;
}

// ---------------- launch ----------------
extern "C" void kernel_launch(void* const* d_in, const int* in_sizes, int n_in,
                              void* d_out, int out_size) {
    const float* feats = (const float*)d_in[0];
    const int*   labels= (const int*)d_in[1];
    const float* W1   = (const float*)d_in[2];
    const float* b1   = (const float*)d_in[3];
    const float* gamma= (const float*)d_in[4];
    const float* beta = (const float*)d_in[5];
    const float* W2   = (const float*)d_in[6];
    const float* b2   = (const float*)d_in[7];
    const float* Wa1  = (const float*)d_in[8];
    const float* ba1  = (const float*)d_in[9];
    const float* Wa2  = (const float*)d_in[10];
    const float* ba2  = (const float*)d_in[11];

    cudaFuncSetAttribute(k_fused, cudaFuncAttributeMaxDynamicSharedMemorySize, DYNB);

    k_prep<<<320, 256>>>(W1, W2);
    k_fused<<<NCONVB + NSAMPB, 256, DYNB>>>(feats, W1, Wa1, labels);
    k_stats<<<128, 256>>>();
    k_proj<<<1024, 128>>>(b1, gamma, beta, b2, ba1, Wa2, ba2);
    k_loss<<<64, 256>>>();
    k_final<<<1, 32>>>((float*)d_out);
}

// round 9
// speedup vs baseline: 3.2484x; 1.1498x over previous
#include <cuda_runtime.h>
#include <cuda_fp16.h>
#include <mma.h>
#include <cstdint>

using namespace nvcuda;

#define CC 2048
#define HWN 4096
#define NCONVB 512
#define NSAMPB 128   // 16 img x 8 K-splits

// ---------------- device scratch ----------------
__device__ __half g_W1h[128*2048];
__device__ float g_W2t[128*128];     // transposed W2: [k][o]
__device__ float g_p1[128*512];      // [ch][block] transposed partials
__device__ float g_p2[128*512];
__device__ float g_mean[128];
__device__ float g_istd[128];
__device__ float g_hs8[8*1024*192];
__device__ float g_tf[1024*128];
__device__ float g_tw[1024];
__device__ float g_loss[16];

// ---------------- helpers ----------------
__device__ __forceinline__ void cpasync16(void* s, const void* g) {
    unsigned sa = (unsigned)__cvta_generic_to_shared(s);
    asm volatile("cp.async.cg.shared.global [%0], [%1], 16;\n" :: "r"(sa), "l"(g));
}
__device__ __forceinline__ void cpcommit() { asm volatile("cp.async.commit_group;\n"); }
template<int N> __device__ __forceinline__ void cpwait() {
    asm volatile("cp.async.wait_group %0;\n" :: "n"(N));
}
__device__ __forceinline__ uint32_t h2u(float x, float y) {
    __half2 h = __floats2half2_rn(x, y);
    return *reinterpret_cast<uint32_t*>(&h);
}

// ---------------- prep: W1 -> half, W2 -> transposed ----------------
__global__ void k_prep(const float* __restrict__ W1, const float* __restrict__ W2) {
    if (blockIdx.x < 256) {
        int idx = blockIdx.x*256 + threadIdx.x;     // 65536 float4
        float4 v = reinterpret_cast<const float4*>(W1)[idx];
        uint2 u; u.x = h2u(v.x, v.y); u.y = h2u(v.z, v.w);
        *reinterpret_cast<uint2*>(g_W1h + idx*4) = u;
    } else {
        int idx = (blockIdx.x - 256)*256 + threadIdx.x;  // 16384 floats
        int o = idx >> 7, k = idx & 127;
        g_W2t[k*128 + o] = W2[idx];
    }
}

// smem: A f16 2 x 8704 | W f16 4 x 10240 = 58368 B
#define DYNB 58368

__global__ __launch_bounds__(256, 2)
void k_fused(const float* __restrict__ feats, const float* __restrict__ W1,
             const float* __restrict__ Wa1,  const int* __restrict__ labels) {
    extern __shared__ char dynC[];
    float* dyn = (float*)dynC;
    __shared__ float r1[256], r2[256];
    const int tid = threadIdx.x;

    if (blockIdx.x >= NCONVB) {
        // ============ sampled path: exact fp32 conv at 64 label==1 pixels ============
        const int sb = blockIdx.x - NCONVB;
        const int z = sb & 7;
        const int b = sb >> 3;
        float* Fs  = dyn;                    // [64][33]
        float* Ws2 = dyn + 64*33;            // [192][33]
        int*   pix = (int*)(dyn + 64*33 + 192*33);

        if (tid < 64) pix[tid] = 0;
        __syncthreads();
        if (tid < 32) {
            const int lane = tid;
            int probe = 0;
            #pragma unroll
            for (int i = lane; i < 64; i += 32) probe |= labels[2*(i*512)+1];
            unsigned any = __ballot_sync(0xffffffffu, probe != 0);
            const bool is64 = (any == 0u);
            const long long* L64 = (const long long*)labels;
            int base = 0;
            for (int c = 0; c < 128; c++) {
                if (base >= 64) break;
                int p = (c << 5) + lane;
                long long v = is64 ? L64[(size_t)b*HWN + p]
                                   : (long long)labels[(size_t)b*HWN + p];
                bool valid = (v == 1);
                unsigned m = __ballot_sync(0xffffffffu, valid);
                int pre = __popc(m & ((1u << lane) - 1u));
                if (valid && base + pre < 64) pix[base + pre] = p;
                base += __popc(m);
            }
        }
        __syncthreads();

        float acc[4][12];
        #pragma unroll
        for (int i = 0; i < 4; i++)
            #pragma unroll
            for (int j = 0; j < 12; j++) acc[i][j] = 0.f;

        const int pg = tid & 15;
        const int cg = tid >> 4;
        const size_t fb = (size_t)b*CC*HWN;
        const int kbase = z * 256;

        for (int chn = 0; chn < 8; chn++) {
            int k0 = kbase + chn*32;
            __syncthreads();
            #pragma unroll
            for (int i = 0; i < 8; i++) {
                int idx = tid + i*256;
                int px = idx >> 5, kk = idx & 31;
                Fs[px*33 + kk] = feats[fb + (size_t)(k0+kk)*HWN + pix[px]];
            }
            #pragma unroll
            for (int i = 0; i < 24; i++) {
                int idx = tid + i*256;
                int r = idx >> 5, kk = idx & 31;
                Ws2[r*33 + kk] = (r < 128) ? W1[r*CC + k0 + kk]
                                           : Wa1[(r-128)*CC + k0 + kk];
            }
            __syncthreads();
            #pragma unroll 4
            for (int kk = 0; kk < 32; kk++) {
                float fv[4];
                #pragma unroll
                for (int i = 0; i < 4; i++) fv[i] = Fs[(pg*4 + i)*33 + kk];
                #pragma unroll
                for (int j = 0; j < 12; j++) {
                    float w = Ws2[(cg*12 + j)*33 + kk];
                    #pragma unroll
                    for (int i = 0; i < 4; i++) acc[i][j] += fv[i]*w;
                }
            }
        }
        #pragma unroll
        for (int i = 0; i < 4; i++)
            #pragma unroll
            for (int j = 0; j < 12; j++)
                g_hs8[(size_t)z*196608 + (b*64 + pg*4 + i)*192 + cg*12 + j] = acc[i][j];
        return;
    }

    // ===== conv1 stats: f16 wmma, M=128 x N=128; A = LDG->reg-convert->STS ===========
    const int cb = blockIdx.x;
    const int b  = cb >> 5;
    const int p0 = (cb & 31) * 128;
    const float* F = feats + (size_t)b*CC*HWN + p0;

    const int wid = tid >> 5;
    const int wr  = wid & 3;    // 32-pixel group
    const int wc  = wid >> 2;   // 64-channel group

    wmma::fragment<wmma::accumulator,16,16,16,half> acc[2][4];
    #pragma unroll
    for (int i = 0; i < 2; i++)
        #pragma unroll
        for (int j = 0; j < 4; j++) wmma::fill_fragment(acc[i][j], __float2half(0.f));

    auto Ah = [&](int s) { return (half*)(dynC + s*8704); };             // [32k][136]
    auto Wh = [&](int s) { return (half*)(dynC + 17408 + s*10240); };    // [128ch][40]

    // per-thread A coords: idx = tid + i*256, k = idx>>5 (0..31), px4 = (idx&31)*4
    float4 ra[4];
    auto ldA = [&](int kc) {
        const float* Fg = F + (size_t)(kc*32)*HWN;
        #pragma unroll
        for (int i = 0; i < 4; i++) {
            int idx = tid + i*256;
            int k = idx >> 5, px4 = (idx & 31) << 2;
            ra[i] = *reinterpret_cast<const float4*>(Fg + (size_t)k*HWN + px4);
        }
    };
    auto stA = [&](int kc) {
        half* Ab = Ah(kc & 1);
        #pragma unroll
        for (int i = 0; i < 4; i++) {
            int idx = tid + i*256;
            int k = idx >> 5, px4 = (idx & 31) << 2;
            uint2 u; u.x = h2u(ra[i].x, ra[i].y); u.y = h2u(ra[i].z, ra[i].w);
            *reinterpret_cast<uint2*>(Ab + k*136 + px4) = u;
        }
    };
    auto issueW = [&](int kc) {
        half* W = Wh(kc & 3);
        const __half* Wg = g_W1h + kc*32;
        #pragma unroll
        for (int i = 0; i < 2; i++) {
            int idx = tid + i*256;
            int ch = idx >> 2, k8 = (idx & 3) << 3;
            cpasync16(W + ch*40 + k8, Wg + ch*2048 + k8);
        }
        cpcommit();
    };
    auto compute = [&](int kc) {
        const half* Ab = Ah(kc & 1);
        const half* Wb = Wh(kc & 3);
        #pragma unroll
        for (int ks = 0; ks < 32; ks += 16) {
            wmma::fragment<wmma::matrix_a,16,16,16,half,wmma::col_major> af[2];
            #pragma unroll
            for (int i = 0; i < 2; i++)
                wmma::load_matrix_sync(af[i], Ab + ks*136 + wr*32 + i*16, 136);
            wmma::fragment<wmma::matrix_b,16,16,16,half,wmma::col_major> bf[4];
            #pragma unroll
            for (int j = 0; j < 4; j++)
                wmma::load_matrix_sync(bf[j], Wb + (wc*64 + j*16)*40 + ks, 40);
            #pragma unroll
            for (int i = 0; i < 2; i++)
                #pragma unroll
                for (int j = 0; j < 4; j++)
                    wmma::mma_sync(acc[i][j], af[i], bf[j], acc[i][j]);
        }
    };

    // prologue
    issueW(0); issueW(1);
    ldA(0); stA(0);
    ldA(1);
    cpwait<1>();          // W(0) ready
    __syncthreads();      // Ah[0] visible

    for (int kc = 0; kc < 64; kc++) {
        if (kc + 1 < 64) stA(kc + 1);      // regs loaded last iter -> other buffer
        if (kc + 2 < 64) ldA(kc + 2);      // LDG early; covered by compute below
        compute(kc);
        if (kc + 2 < 64) { issueW(kc + 2); cpwait<1>(); }   // W(kc+1) ready
        else             { cpwait<0>(); }
        __syncthreads();
    }

    // Epilogue: f16 acc -> smem -> per-channel sum/sumsq, transposed partials
    half* Cs16 = (half*)dynC;   // [128 px][136] = 34816 B, fits
    #pragma unroll
    for (int i = 0; i < 2; i++)
        #pragma unroll
        for (int j = 0; j < 4; j++)
            wmma::store_matrix_sync(Cs16 + (wr*32 + i*16)*136 + wc*64 + j*16,
                                    acc[i][j], 136, wmma::mem_row_major);
    __syncthreads();
    {
        const int ch = tid & 127;
        const int sg = tid >> 7;
        float s = 0.f, s2 = 0.f;
        #pragma unroll 4
        for (int p = sg*64; p < sg*64 + 64; p++) {
            float v = __half2float(Cs16[p*136 + ch]);
            s += v; s2 += v*v;
        }
        r1[tid] = s; r2[tid] = s2;
        __syncthreads();
        if (tid < 128) {
            g_p1[tid*512 + cb] = r1[tid] + r1[tid+128];
            g_p2[tid*512 + cb] = r2[tid] + r2[tid+128];
        }
    }
}

// ---------------- stats: reduce per-block partials (grid 128 = one ch each) ----------
__global__ void k_stats() {
    __shared__ float sS[256], sS2[256];
    const int ch = blockIdx.x;
    const int t = threadIdx.x;
    if (ch == 0 && t < 16) g_loss[t] = 0.f;
    float S  = g_p1[ch*512 + t] + g_p1[ch*512 + t + 256];
    float S2 = g_p2[ch*512 + t] + g_p2[ch*512 + t + 256];
    sS[t] = S; sS2[t] = S2;
    __syncthreads();
    for (int s = 128; s > 0; s >>= 1) {
        if (t < s) { sS[t] += sS[t+s]; sS2[t] += sS2[t+s]; }
        __syncthreads();
    }
    if (t == 0) {
        float m   = sS[0] * (1.f/65536.f);
        float var = sS2[0] * (1.f/65536.f) - m*m;
        g_mean[ch] = m;
        g_istd[ch] = rsqrtf(var + 1e-5f);
    }
}

// ---------------- per-pixel: BN + conv2 (coalesced W2t) + normalize + attention -------
__global__ void k_proj(const float* __restrict__ b1, const float* __restrict__ gamma,
                       const float* __restrict__ beta, const float* __restrict__ b2,
                       const float* __restrict__ ba1, const float* __restrict__ Wa2,
                       const float* __restrict__ ba2) {
    __shared__ float xr[128];
    __shared__ float ar[64];
    __shared__ float red[128];
    const int t = threadIdx.x;
    const int pid = blockIdx.x;
    {
        float h = b1[t];
        #pragma unroll
        for (int z = 0; z < 8; z++) h += g_hs8[(size_t)z*196608 + pid*192 + t];
        float xn = (h - (g_mean[t] + b1[t])) * g_istd[t] * gamma[t] + beta[t];
        xr[t] = fmaxf(xn, 0.f);
    }
    if (t < 64) {
        float ha = 0.f;
        #pragma unroll
        for (int z = 0; z < 8; z++) ha += g_hs8[(size_t)z*196608 + pid*192 + 128 + t];
        ar[t] = fmaxf(ha + ba1[t], 0.f);
    }
    __syncthreads();

    float acc = b2[t];
    #pragma unroll 8
    for (int k = 0; k < 128; k++) acc += g_W2t[k*128 + t] * xr[k];

    red[t] = acc*acc;
    __syncthreads();
    for (int s = 64; s > 0; s >>= 1) { if (t < s) red[t] += red[t+s]; __syncthreads(); }
    float rinv = 1.f / fmaxf(sqrtf(red[0]), 1e-12f);
    g_tf[pid*128 + t] = acc * rinv;

    if (t < 32) {
        float z = Wa2[t]*ar[t] + Wa2[t+32]*ar[t+32];
        #pragma unroll
        for (int o = 16; o > 0; o >>= 1) z += __shfl_down_sync(0xffffffffu, z, o);
        if (t == 0) g_tw[pid] = 1.f / (1.f + expf(-(z + ba2[0])));
    }
}

// ---------------- contrastive loss (grid 64 = 4 row-blocks per image) ----------------
__global__ __launch_bounds__(256) void k_loss() {
    __shared__ float tf[64*128];
    __shared__ float tw[64];
    __shared__ float red[256];
    const int t = threadIdx.x;
    const int b  = blockIdx.x >> 2;
    const int rg = blockIdx.x & 3;

    #pragma unroll
    for (int i = 0; i < 8; i++)
        reinterpret_cast<float4*>(tf)[t + i*256] =
            reinterpret_cast<const float4*>(g_tf + b*8192)[t + i*256];
    if (t < 64) tw[t] = g_tw[b*64 + t];
    __syncthreads();

    const int lr = t >> 4;
    const int cg = t & 15;
    const int i  = rg*16 + lr;

    float s[4];
    {
        float a0 = 0.f, a1 = 0.f, a2 = 0.f, a3 = 0.f;
        const float4* fi = reinterpret_cast<const float4*>(tf + i*128);
        const float4* c0 = reinterpret_cast<const float4*>(tf + (cg*4+0)*128);
        const float4* c1 = reinterpret_cast<const float4*>(tf + (cg*4+1)*128);
        const float4* c2 = reinterpret_cast<const float4*>(tf + (cg*4+2)*128);
        const float4* c3 = reinterpret_cast<const float4*>(tf + (cg*4+3)*128);
        #pragma unroll 8
        for (int k4 = 0; k4 < 32; k4++) {
            float4 a = fi[k4];
            float4 v0 = c0[k4], v1 = c1[k4], v2 = c2[k4], v3 = c3[k4];
            a0 += a.x*v0.x + a.y*v0.y + a.z*v0.z + a.w*v0.w;
            a1 += a.x*v1.x + a.y*v1.y + a.z*v1.z + a.w*v1.w;
            a2 += a.x*v2.x + a.y*v2.y + a.z*v2.z + a.w*v2.w;
            a3 += a.x*v3.x + a.y*v3.y + a.z*v3.z + a.w*v3.w;
        }
        s[0] = a0*10.f; s[1] = a1*10.f; s[2] = a2*10.f; s[3] = a3*10.f;
    }
    float d = expf(s[0]) + expf(s[1]) + expf(s[2]) + expf(s[3]);
    d += __shfl_xor_sync(0xffffffffu, d, 1);
    d += __shfl_xor_sync(0xffffffffu, d, 2);
    d += __shfl_xor_sync(0xffffffffu, d, 4);
    d += __shfl_xor_sync(0xffffffffu, d, 8);

    float lacc = 0.f;
    float twi = tw[i];
    #pragma unroll
    for (int j = 0; j < 4; j++) {
        int jj = cg*4 + j;
        if (s[j] > 0.7f && jj != i)
            lacc += twi * tw[jj] * logf(expf(s[j])/d + 1e-10f);
    }
    red[t] = lacc;
    __syncthreads();
    for (int sft = 128; sft > 0; sft >>= 1) { if (t < sft) red[t] += red[t+sft]; __syncthreads(); }
    if (t == 0) atomicAdd(&g_loss[b], red[0]);
}

// ---------------- final: per-image normalize + mean * LOSS_WEIGHT ----------------
__global__ void k_final(float* out) {
    int t = threadIdx.x;
    float v = 0.f;
    if (t < 16) {
        float tsum = 0.f;
        for (int j = 0; j < 64; j++) tsum += g_tw[t*64 + j];
        v = -(0.1f/0.07f) * g_loss[t] / tsum;
    }
    #pragma unroll
    for (int o = 16; o > 0; o >>= 1) v += __shfl_down_sync(0xffffffffu, v, o);
    if (t == 0) out[0] = (v / 16.0f) * 0.1f;
}

// ---------------- launch ----------------
extern "C" void kernel_launch(void* const* d_in, const int* in_sizes, int n_in,
                              void* d_out, int out_size) {
    const float* feats = (const float*)d_in[0];
    const int*   labels= (const int*)d_in[1];
    const float* W1   = (const float*)d_in[2];
    const float* b1   = (const float*)d_in[3];
    const float* gamma= (const float*)d_in[4];
    const float* beta = (const float*)d_in[5];
    const float* W2   = (const float*)d_in[6];
    const float* b2   = (const float*)d_in[7];
    const float* Wa1  = (const float*)d_in[8];
    const float* ba1  = (const float*)d_in[9];
    const float* Wa2  = (const float*)d_in[10];
    const float* ba2  = (const float*)d_in[11];

    cudaFuncSetAttribute(k_fused, cudaFuncAttributeMaxDynamicSharedMemorySize, DYNB);

    k_prep<<<320, 256>>>(W1, W2);
    k_fused<<<NCONVB + NSAMPB, 256, DYNB>>>(feats, W1, Wa1, labels);
    k_stats<<<128, 256>>>();
    k_proj<<<1024, 128>>>(b1, gamma, beta, b2, ba1, Wa2, ba2);
    k_loss<<<64, 256>>>();
    k_final<<<1, 32>>>((float*)d_out);
}